// round 15
// baseline (speedup 1.0000x reference)
#include <cuda_runtime.h>
#include <math.h>
#include <stdint.h>

#define BQ   4
#define LQ   2048
#define DM   256
#define HH   8
#define HD   2048
#define DFF  1024
#define UK   40
#define NTOP 5
#define ROWS (BQ*LQ)
#define NCH  8
#define CHS  (LQ/NCH)

__device__ float g_x[ROWS*DM];
__device__ float g_z[ROWS*HD];
__device__ float g_hid[ROWS*DFF];
__device__ float g_y[ROWS*DM];
__device__ float g_ysplit[4*ROWS*DM];
__device__ float g_M[BQ*HH*LQ];
__device__ int   g_top[BQ*HH*NTOP];
__device__ float g_nx2[BQ*DM];
__device__ float g_A[2*DM*HD];
__device__ float g_w2[2*HH*DM];
__device__ float g_D[ROWS*HH];
__device__ float g_pm[BQ*HH*NCH*NTOP];
__device__ float g_ps[BQ*HH*NCH*NTOP];
__device__ float g_pxb[BQ*HH*NCH*NTOP*DM];

__device__ __forceinline__ float warpSum(float v) {
    #pragma unroll
    for (int o = 16; o > 0; o >>= 1) v += __shfl_xor_sync(0xffffffffu, v, o);
    return v;
}
__device__ __forceinline__ float warpMax(float v) {
    #pragma unroll
    for (int o = 16; o > 0; o >>= 1) v = fmaxf(v, __shfl_xor_sync(0xffffffffu, v, o));
    return v;
}
__device__ __forceinline__ float gelu_exact(float x) {
    return 0.5f * x * (1.0f + erff(x * 0.70710678118654752440f));
}
__device__ __forceinline__ float blockSum256(float v, float* sh) {
    int t = threadIdx.x;
    __syncthreads();
    sh[t] = v; __syncthreads();
    #pragma unroll
    for (int s = 128; s > 0; s >>= 1) {
        if (t < s) sh[t] += sh[t + s];
        __syncthreads();
    }
    return sh[0];
}
__device__ __forceinline__ void mma_tf32(float c[4], const uint32_t a[4],
                                         const uint32_t b[2]) {
    asm volatile(
        "mma.sync.aligned.m16n8k8.row.col.f32.tf32.tf32.f32 "
        "{%0,%1,%2,%3}, {%4,%5,%6,%7}, {%8,%9}, {%0,%1,%2,%3};\n"
        : "+f"(c[0]), "+f"(c[1]), "+f"(c[2]), "+f"(c[3])
        : "r"(a[0]), "r"(a[1]), "r"(a[2]), "r"(a[3]), "r"(b[0]), "r"(b[1]));
}
__device__ __forceinline__ float dot8(float4 a0, float4 a1, float4 b0, float4 b1) {
    return a0.x*b0.x + a0.y*b0.y + a0.z*b0.z + a0.w*b0.w
         + a1.x*b1.x + a1.y*b1.y + a1.z*b1.z + a1.w*b1.w;
}
__device__ __forceinline__ void split_tf32(float x, uint32_t& hi, uint32_t& lo) {
    hi = __float_as_uint(x) & 0xFFFFE000u;
    lo = __float_as_uint(x - __uint_as_float(hi));
}
__device__ __forceinline__ void cp_async16(void* smem_dst, const void* gsrc) {
    uint32_t s = (uint32_t)__cvta_generic_to_shared(smem_dst);
    asm volatile("cp.async.cg.shared.global [%0], [%1], 16;" :: "r"(s), "l"(gsrc));
}
#define CP_COMMIT() asm volatile("cp.async.commit_group;")
#define CP_WAIT1()  asm volatile("cp.async.wait_group 1;" ::: "memory")

// ------- 3xTF32 GEMM: fp32 smem, split at frag load, cp.async 3-stage ----------
#define TGK 16
#define ASTR 20
#define BSTR 136
#define A_FLOATS (128 * ASTR)
#define B_FLOATS (TGK * BSTR)
#define STG (A_FLOATS + B_FLOATS)
#define TG_SMEM_BYTES (3 * STG * 4)    // 56832

template<int ACT, int BIAS, int SPLIT>
__global__ __launch_bounds__(256, 2) void tgemm3(
    const float* __restrict__ A, const float* __restrict__ B,
    const float* __restrict__ bias, float* __restrict__ C,
    int M, int N, int K)
{
    extern __shared__ float smem[];

    const int t = threadIdx.x;
    const int bm0 = blockIdx.y * 128;
    const int bn0 = blockIdx.x * 128;
    const int kz = SPLIT ? blockIdx.z : 0;
    const int Kc = SPLIT ? (K / gridDim.z) : K;
    if (SPLIT) C += (size_t)kz * M * N;

    const int arow = t >> 2, acol = (t & 3) * 4;
    const int brow = t >> 5, bcol = (t & 31) * 4;
    const float* Ag = A + (size_t)(bm0 + arow) * K + (size_t)kz * Kc + acol;
    const float* Bg = B + (size_t)((size_t)kz * Kc + brow) * N + bn0 + bcol;

    const int wid = t >> 5, lane = t & 31;
    const int wm = wid & 3, wn = wid >> 2;
    const int mrow = wm * 32, ncol = wn * 64;
    const int g = lane >> 2, kq = lane & 3;

    float acc[2][8][4];
    #pragma unroll
    for (int i = 0; i < 2; i++)
        #pragma unroll
        for (int j = 0; j < 8; j++)
            #pragma unroll
            for (int c = 0; c < 4; c++) acc[i][j][c] = 0.f;

    const int nIter = Kc / TGK;

    auto commit_stage = [&](int it) {
        if (it < nIter) {
            int st = it % 3;
            float* As = smem + st * STG;
            float* Bs = As + A_FLOATS;
            const float* Aq = Ag + it * TGK;
            const float* Bq = Bg + (size_t)(it * TGK) * N;
            cp_async16(&As[arow * ASTR + acol], Aq);
            cp_async16(&As[(arow + 64) * ASTR + acol], Aq + (size_t)64 * K);
            cp_async16(&Bs[brow * BSTR + bcol], Bq);
            cp_async16(&Bs[(brow + 8) * BSTR + bcol], Bq + (size_t)8 * N);
        }
        CP_COMMIT();
    };

    commit_stage(0);
    commit_stage(1);

    for (int it = 0; it < nIter; it++) {
        CP_WAIT1();
        __syncthreads();
        commit_stage(it + 2);

        const float* As = smem + (it % 3) * STG;
        const float* Bs = As + A_FLOATS;
        #pragma unroll
        for (int kk = 0; kk < TGK; kk += 8) {
            uint32_t ah[2][4], al[2][4];
            #pragma unroll
            for (int mt = 0; mt < 2; mt++) {
                int base = (mrow + mt * 16 + g) * ASTR + kk + kq;
                split_tf32(As[base],                ah[mt][0], al[mt][0]);
                split_tf32(As[base + 8 * ASTR],     ah[mt][1], al[mt][1]);
                split_tf32(As[base + 4],            ah[mt][2], al[mt][2]);
                split_tf32(As[base + 8 * ASTR + 4], ah[mt][3], al[mt][3]);
            }
            #pragma unroll
            for (int nt = 0; nt < 8; nt++) {
                int base = (kk + kq) * BSTR + ncol + nt * 8 + g;
                uint32_t bh[2], bl[2];
                split_tf32(Bs[base],            bh[0], bl[0]);
                split_tf32(Bs[base + 4 * BSTR], bh[1], bl[1]);
                #pragma unroll
                for (int mt = 0; mt < 2; mt++) {
                    mma_tf32(acc[mt][nt], ah[mt], bl);
                    mma_tf32(acc[mt][nt], al[mt], bh);
                    mma_tf32(acc[mt][nt], ah[mt], bh);
                }
            }
        }
    }

    #pragma unroll
    for (int mt = 0; mt < 2; mt++) {
        int row = bm0 + mrow + mt * 16 + g;
        #pragma unroll
        for (int nt = 0; nt < 8; nt++) {
            int col = bn0 + ncol + nt * 8 + 2 * kq;
            float b0 = 0.f, b1 = 0.f;
            if (BIAS) { b0 = bias[col]; b1 = bias[col + 1]; }
            float v0 = acc[mt][nt][0] + b0;
            float v1 = acc[mt][nt][1] + b1;
            float v2 = acc[mt][nt][2] + b0;
            float v3 = acc[mt][nt][3] + b1;
            if (ACT == 1) {
                v0 = gelu_exact(v0); v1 = gelu_exact(v1);
                v2 = gelu_exact(v2); v3 = gelu_exact(v3);
            }
            *(float2*)(C + (size_t)row * N + col)       = make_float2(v0, v1);
            *(float2*)(C + (size_t)(row + 8) * N + col) = make_float2(v2, v3);
        }
    }
}

// ---------------- A_h = Wq_h @ Wk_h^T  (fp32, exact)  grid (2,2,8) -------------
__global__ __launch_bounds__(256) void precomp_A(
    const float* __restrict__ Wq, const float* __restrict__ Wk,
    float* __restrict__ Aout)
{
    int h = blockIdx.z;
    int m0 = blockIdx.y * 128, n0 = blockIdx.x * 128;
    __shared__ float sa[8][128];
    __shared__ float sb[8][128];
    int t = threadIdx.x, tx = t & 15, ty = t >> 4;
    int lrow = t >> 1, lk = (t & 1) * 4;

    float acc[8][8];
    #pragma unroll
    for (int i = 0; i < 8; i++)
        #pragma unroll
        for (int j = 0; j < 8; j++) acc[i][j] = 0.f;

    for (int k0 = 0; k0 < DM; k0 += 8) {
        float4 a = *(const float4*)(Wq + (size_t)(m0 + lrow) * HD + h * DM + k0 + lk);
        float4 b = *(const float4*)(Wk + (size_t)(n0 + lrow) * HD + h * DM + k0 + lk);
        sa[lk + 0][lrow] = a.x; sa[lk + 1][lrow] = a.y;
        sa[lk + 2][lrow] = a.z; sa[lk + 3][lrow] = a.w;
        sb[lk + 0][lrow] = b.x; sb[lk + 1][lrow] = b.y;
        sb[lk + 2][lrow] = b.z; sb[lk + 3][lrow] = b.w;
        __syncthreads();
        #pragma unroll
        for (int kk = 0; kk < 8; kk++) {
            float ra[8], rb[8];
            #pragma unroll
            for (int i = 0; i < 8; i++) ra[i] = sa[kk][ty * 8 + i];
            #pragma unroll
            for (int j = 0; j < 8; j++) rb[j] = sb[kk][tx * 8 + j];
            #pragma unroll
            for (int i = 0; i < 8; i++)
                #pragma unroll
                for (int j = 0; j < 8; j++) acc[i][j] += ra[i] * rb[j];
        }
        __syncthreads();
    }
    #pragma unroll
    for (int i = 0; i < 8; i++)
        #pragma unroll
        for (int j = 0; j < 8; j++)
            Aout[(size_t)(m0 + ty * 8 + i) * HD + h * DM + n0 + tx * 8 + j] = acc[i][j];
}

__global__ void precomp_w2(const float* __restrict__ Wk,
                           const float* __restrict__ bq, float* __restrict__ w2)
{
    int gw = (blockIdx.x * 256 + threadIdx.x) >> 5;
    int lane = threadIdx.x & 31;
    int h = gw >> 8, m = gw & 255;
    const float* wr = Wk + (size_t)m * HD + h * DM + lane * 8;
    const float* br = bq + h * DM + lane * 8;
    float4 a0 = *(const float4*)wr, a1 = *(const float4*)(wr + 4);
    float4 b0 = *(const float4*)br, b1 = *(const float4*)(br + 4);
    float p = warpSum(dot8(a0, a1, b0, b1));
    if (lane == 0) w2[h * 256 + m] = p;
}

__global__ __launch_bounds__(256) void dvec_kernel(
    const float* __restrict__ x, const float* __restrict__ w2,
    float* __restrict__ D)
{
    __shared__ float ws[HH * DM];
    int t = threadIdx.x;
    for (int i = t; i < HH * DM; i += 256) ws[i] = w2[i];
    __syncthreads();
    int gw = (blockIdx.x * 256 + t) >> 5;
    int lane = t & 31;
    const float* xr = x + (size_t)gw * DM + lane * 8;
    float4 xa = *(const float4*)xr, xb = *(const float4*)(xr + 4);
    float out = 0.f;
    #pragma unroll
    for (int h = 0; h < 8; h++) {
        const float* wr = ws + h * DM + lane * 8;
        float4 w0 = *(const float4*)wr, w1 = *(const float4*)(wr + 4);
        float p = warpSum(dot8(xa, xb, w0, w1));
        if (lane == h) out = p;
    }
    if (lane < 8) D[(size_t)gw * HH + lane] = out;
}

__global__ __launch_bounds__(256) void compute_M2(
    const float* __restrict__ Z, const float* __restrict__ x,
    const int* __restrict__ idx, const float* __restrict__ D,
    float* __restrict__ Mout)
{
    int t = threadIdx.x, lane = t & 31;
    int gw = (blockIdx.x * 256 + t) >> 5;
    int l = gw & (LQ - 1), b = gw >> 11;

    float4 z0[8], z1[8];
    const float* zr = Z + (size_t)gw * HD;
    #pragma unroll
    for (int h = 0; h < 8; h++) {
        z0[h] = *(const float4*)(zr + h * DM + lane * 8);
        z1[h] = *(const float4*)(zr + h * DM + lane * 8 + 4);
    }
    float mx[8], sm[8];
    #pragma unroll
    for (int h = 0; h < 8; h++) { mx[h] = -3.4e38f; sm[h] = 0.f; }

    for (int u = 0; u < UK; u++) {
        int s = __ldg(&idx[l * UK + u]);
        const float* xr = x + ((size_t)(b * LQ + s)) * DM + lane * 8;
        float4 xa = *(const float4*)xr, xb = *(const float4*)(xr + 4);
        const float* dp = D + (size_t)(b * LQ + s) * HH;
        float p[8];
        #pragma unroll
        for (int h = 0; h < 8; h++) p[h] = dot8(z0[h], z1[h], xa, xb);
        #pragma unroll
        for (int h = 0; h < 8; h++) {
            p[h] = warpSum(p[h]) + __ldg(&dp[h]);
            mx[h] = fmaxf(mx[h], p[h]);
            sm[h] += p[h];
        }
    }
    float out = 0.f;
    #pragma unroll
    for (int h = 0; h < 8; h++)
        if (lane == h) out = mx[h] - sm[h] * (1.0f / LQ);
    if (lane < 8) Mout[((size_t)(b * 8 + lane)) * LQ + l] = out;
}

__global__ __launch_bounds__(256) void top5_kernel(
    const float* __restrict__ M, int* __restrict__ topi)
{
    int bh = blockIdx.x, tid = threadIdx.x;
    __shared__ float sM[LQ];
    __shared__ float sv[256];
    __shared__ int   si[256];
    for (int i = tid; i < LQ; i += 256) sM[i] = M[(size_t)bh * LQ + i];
    __syncthreads();
    for (int t = 0; t < NTOP; t++) {
        float best = -3.4e38f; int bi = LQ;
        for (int i = tid; i < LQ; i += 256) {
            float v = sM[i];
            if (v > best) { best = v; bi = i; }
        }
        sv[tid] = best; si[tid] = bi;
        __syncthreads();
        for (int s = 128; s > 0; s >>= 1) {
            if (tid < s) {
                if (sv[tid + s] > sv[tid] ||
                    (sv[tid + s] == sv[tid] && si[tid + s] < si[tid])) {
                    sv[tid] = sv[tid + s]; si[tid] = si[tid + s];
                }
            }
            __syncthreads();
        }
        if (tid == 0) { topi[bh * NTOP + t] = si[0]; sM[si[0]] = -3.4e38f; }
        __syncthreads();
    }
}

// ---- ctx phase A: one block per (b,h,chunk); partial softmax + partial xbar ---
__global__ __launch_bounds__(256) void ctxA(
    const float* __restrict__ Z, const float* __restrict__ x,
    const int* __restrict__ topi, const float* __restrict__ D,
    float* __restrict__ pm, float* __restrict__ ps, float* __restrict__ pxb,
    int only_last)
{
    int blk = blockIdx.x;
    int ch = blk & (NCH - 1), bh = blk >> 3;
    int h = bh & 7, b = bh >> 3;
    int tid = threadIdx.x, lane = tid & 31, w = tid >> 5;

    __shared__ float sc[NTOP][CHS];
    __shared__ float xbs[NTOP * DM];
    __shared__ float lmax[NTOP], lsum[NTOP];
    __shared__ int rtop[NTOP];
    if (tid < NTOP) rtop[tid] = topi[bh * NTOP + tid];
    __syncthreads();

    if (only_last) {
        bool has = false;
        #pragma unroll
        for (int i = 0; i < NTOP; i++) has |= (rtop[i] == LQ - 1);
        if (!has) return;
    }

    int s0 = ch * CHS;
    {
        float4 za[NTOP], zb[NTOP];
        #pragma unroll
        for (int i = 0; i < NTOP; i++) {
            int r = rtop[i];
            const float* zr = Z + ((size_t)(b * LQ + r)) * HD + h * DM + lane * 8;
            za[i] = *(const float4*)zr;
            zb[i] = *(const float4*)(zr + 4);
        }
        for (int sl = w; sl < CHS; sl += 8) {
            int s = s0 + sl;
            const float* xr = x + ((size_t)(b * LQ + s)) * DM + lane * 8;
            float4 xa = *(const float4*)xr, xb2 = *(const float4*)(xr + 4);
            float p[NTOP];
            #pragma unroll
            for (int i = 0; i < NTOP; i++) p[i] = dot8(za[i], zb[i], xa, xb2);
            #pragma unroll
            for (int i = 0; i < NTOP; i++) p[i] = warpSum(p[i]);
            if (lane == 0) {
                float dj = D[(size_t)(b * LQ + s) * HH + h];
                #pragma unroll
                for (int i = 0; i < NTOP; i++) sc[i][sl] = p[i] + dj;
            }
        }
    }
    __syncthreads();

    if (w < NTOP) {
        int i = w;
        float m = -3.4e38f;
        for (int sl = lane; sl < CHS; sl += 32) m = fmaxf(m, sc[i][sl]);
        m = warpMax(m);
        float ls = 0.f;
        for (int sl = lane; sl < CHS; sl += 32) {
            float e = expf(sc[i][sl] - m);
            sc[i][sl] = e;
            ls += e;
        }
        ls = warpSum(ls);
        if (lane == 0) { lmax[i] = m; lsum[i] = ls; }
    }
    for (int j = tid; j < NTOP * DM; j += 256) xbs[j] = 0.f;
    __syncthreads();

    {
        int sl0 = w * 32;
        float accv[NTOP][8];
        #pragma unroll
        for (int i = 0; i < NTOP; i++)
            #pragma unroll
            for (int j = 0; j < 8; j++) accv[i][j] = 0.f;
        for (int sl = sl0; sl < sl0 + 32; sl++) {
            const float* xr = x + ((size_t)(b * LQ + s0 + sl)) * DM + lane * 8;
            float4 xa = *(const float4*)xr, xb2 = *(const float4*)(xr + 4);
            float xv[8] = {xa.x, xa.y, xa.z, xa.w, xb2.x, xb2.y, xb2.z, xb2.w};
            #pragma unroll
            for (int i = 0; i < NTOP; i++) {
                float e = sc[i][sl];
                #pragma unroll
                for (int j = 0; j < 8; j++) accv[i][j] += e * xv[j];
            }
        }
        #pragma unroll
        for (int i = 0; i < NTOP; i++)
            #pragma unroll
            for (int j = 0; j < 8; j++)
                atomicAdd(&xbs[i * DM + lane * 8 + j], accv[i][j]);
    }
    __syncthreads();

    if (tid < NTOP) {
        pm[(size_t)(bh * NCH + ch) * NTOP + tid] = lmax[tid];
        ps[(size_t)(bh * NCH + ch) * NTOP + tid] = lsum[tid];
    }
    {
        int d = tid;
        #pragma unroll
        for (int i = 0; i < NTOP; i++)
            pxb[((size_t)(bh * NCH + ch) * NTOP + i) * DM + d] = xbs[i * DM + d];
    }
}

// ---- ctx phase B fused with Wo scatter: combine partials, ctx=xbar@Wv+bv,
// ---- then newx_r += ctx@Wo (atomicAdd). only_last=1: dest is nx2[b][d].
__global__ __launch_bounds__(256) void ctxB2(
    const float* __restrict__ Wv, const float* __restrict__ bv,
    const int* __restrict__ topi,
    const float* __restrict__ pm, const float* __restrict__ ps,
    const float* __restrict__ pxb, const float* __restrict__ Wo,
    float* __restrict__ dest, int only_last)
{
    int bh = blockIdx.x;
    int h = bh & 7, b = bh >> 3;
    int tid = threadIdx.x;

    __shared__ float xb[NTOP * DM];
    __shared__ float cs[NTOP * DM];
    __shared__ float gmax[NTOP], ginv[NTOP];
    __shared__ float sscale[NTOP * NCH];
    __shared__ int rtop[NTOP];
    if (tid < NTOP) rtop[tid] = topi[bh * NTOP + tid];
    __syncthreads();

    if (only_last) {
        bool has = false;
        #pragma unroll
        for (int i = 0; i < NTOP; i++) has |= (rtop[i] == LQ - 1);
        if (!has) return;
    }

    if (tid < NTOP) {
        int i = tid;
        float gm = -3.4e38f;
        #pragma unroll
        for (int c = 0; c < NCH; c++)
            gm = fmaxf(gm, pm[(size_t)(bh * NCH + c) * NTOP + i]);
        gmax[i] = gm;
    }
    __syncthreads();
    if (tid < NTOP * NCH) {
        int i = tid / NCH, c = tid % NCH;
        sscale[i * NCH + c] =
            expf(pm[(size_t)(bh * NCH + c) * NTOP + i] - gmax[i]);
    }
    __syncthreads();
    if (tid < NTOP) {
        int i = tid;
        float tot = 0.f;
        #pragma unroll
        for (int c = 0; c < NCH; c++)
            tot += ps[(size_t)(bh * NCH + c) * NTOP + i] * sscale[i * NCH + c];
        ginv[i] = 1.0f / tot;
    }
    __syncthreads();

    {   // combine xbar
        int d = tid;
        #pragma unroll
        for (int i = 0; i < NTOP; i++) {
            float acc = 0.f;
            #pragma unroll
            for (int c = 0; c < NCH; c++)
                acc += pxb[((size_t)(bh * NCH + c) * NTOP + i) * DM + d]
                     * sscale[i * NCH + c];
            xb[i * DM + d] = acc * ginv[i];
        }
    }
    __syncthreads();

    {   // ctx[i][d] = bv + sum_c xbar[i][c]*Wv[c][h*DM+d]
        int d = tid;
        float acc5[NTOP];
        float bvd = bv[h * DM + d];
        #pragma unroll
        for (int i = 0; i < NTOP; i++) acc5[i] = bvd;
        const float* wp = Wv + h * DM + d;
        #pragma unroll 4
        for (int c = 0; c < DM; c++) {
            float wv = wp[(size_t)c * HD];
            #pragma unroll
            for (int i = 0; i < NTOP; i++) acc5[i] += xb[i * DM + c] * wv;
        }
        #pragma unroll
        for (int i = 0; i < NTOP; i++) cs[i * DM + d] = acc5[i];
    }
    __syncthreads();

    {   // scatter: newx[r_i] += ctx_i @ Wo_h  (atomicAdd)
        int d = tid;
        const float* w = Wo + (size_t)(h * DM) * DM + d;
        #pragma unroll
        for (int i = 0; i < NTOP; i++) {
            int r = rtop[i];
            if (only_last && r != LQ - 1) continue;
            float acc = 0.f;
            #pragma unroll 4
            for (int c = 0; c < DM; c++) acc += cs[i * DM + c] * w[(size_t)c * DM];
            if (only_last) atomicAdd(&dest[b * DM + d], acc);
            else atomicAdd(&dest[((size_t)b * LQ + r) * DM + d], acc);
        }
    }
}

__global__ void fill_bias_kernel(float* __restrict__ out,
                                 const float* __restrict__ bias, int rows)
{
    int gid = blockIdx.x * blockDim.x + threadIdx.x;
    if (gid < rows * DM) out[gid] = bias[gid & (DM - 1)];
}

// x = LN(x + y + bias?) ; bias may be null
__global__ __launch_bounds__(256) void add_ln_kernel(
    float* __restrict__ x, const float* __restrict__ y,
    const float* __restrict__ bias,
    const float* __restrict__ g, const float* __restrict__ bt, int rows)
{
    int gid = blockIdx.x * 256 + threadIdx.x;
    int warp = gid >> 5, lane = gid & 31;
    if (warp >= rows) return;
    float* xr = x + (size_t)warp * DM + lane * 8;
    const float* yr = y + (size_t)warp * DM + lane * 8;
    float4 x0 = *(float4*)xr, x1 = *(float4*)(xr + 4);
    float4 y0 = *(const float4*)yr, y1 = *(const float4*)(yr + 4);
    float v[8] = {x0.x+y0.x, x0.y+y0.y, x0.z+y0.z, x0.w+y0.w,
                  x1.x+y1.x, x1.y+y1.y, x1.z+y1.z, x1.w+y1.w};
    if (bias) {
        const float* br = bias + lane * 8;
        float4 b0 = *(const float4*)br, b1 = *(const float4*)(br + 4);
        float bb[8] = {b0.x,b0.y,b0.z,b0.w,b1.x,b1.y,b1.z,b1.w};
        #pragma unroll
        for (int t = 0; t < 8; t++) v[t] += bb[t];
    }
    float s = 0.f;
    #pragma unroll
    for (int t = 0; t < 8; t++) s += v[t];
    s = warpSum(s);
    float mean = s * (1.0f / DM);
    float vs = 0.f;
    #pragma unroll
    for (int t = 0; t < 8; t++) { float d = v[t] - mean; vs += d * d; }
    vs = warpSum(vs);
    float rstd = rsqrtf(vs * (1.0f / DM) + 1e-5f);
    float o[8];
    #pragma unroll
    for (int t = 0; t < 8; t++)
        o[t] = (v[t] - mean) * rstd * g[lane * 8 + t] + bt[lane * 8 + t];
    *(float4*)xr       = make_float4(o[0], o[1], o[2], o[3]);
    *(float4*)(xr + 4) = make_float4(o[4], o[5], o[6], o[7]);
}

// x = LN(x + p0+p1+p2+p3 + bias)  — deterministic split-K combine
__global__ __launch_bounds__(256) void add_ln4_kernel(
    float* __restrict__ x, const float* __restrict__ p,
    const float* __restrict__ bias,
    const float* __restrict__ g, const float* __restrict__ bt, int rows)
{
    int gid = blockIdx.x * 256 + threadIdx.x;
    int warp = gid >> 5, lane = gid & 31;
    if (warp >= rows) return;
    float* xr = x + (size_t)warp * DM + lane * 8;
    float4 x0 = *(float4*)xr, x1 = *(float4*)(xr + 4);
    float v[8] = {x0.x, x0.y, x0.z, x0.w, x1.x, x1.y, x1.z, x1.w};
    #pragma unroll
    for (int q = 0; q < 4; q++) {
        const float* yr = p + (size_t)q * ROWS * DM + (size_t)warp * DM + lane * 8;
        float4 y0 = *(const float4*)yr, y1 = *(const float4*)(yr + 4);
        float yy[8] = {y0.x,y0.y,y0.z,y0.w,y1.x,y1.y,y1.z,y1.w};
        #pragma unroll
        for (int t = 0; t < 8; t++) v[t] += yy[t];
    }
    {
        const float* br = bias + lane * 8;
        float4 b0 = *(const float4*)br, b1 = *(const float4*)(br + 4);
        float bb[8] = {b0.x,b0.y,b0.z,b0.w,b1.x,b1.y,b1.z,b1.w};
        #pragma unroll
        for (int t = 0; t < 8; t++) v[t] += bb[t];
    }
    float s = 0.f;
    #pragma unroll
    for (int t = 0; t < 8; t++) s += v[t];
    s = warpSum(s);
    float mean = s * (1.0f / DM);
    float vs = 0.f;
    #pragma unroll
    for (int t = 0; t < 8; t++) { float d = v[t] - mean; vs += d * d; }
    vs = warpSum(vs);
    float rstd = rsqrtf(vs * (1.0f / DM) + 1e-5f);
    float o[8];
    #pragma unroll
    for (int t = 0; t < 8; t++)
        o[t] = (v[t] - mean) * rstd * g[lane * 8 + t] + bt[lane * 8 + t];
    *(float4*)xr       = make_float4(o[0], o[1], o[2], o[3]);
    *(float4*)(xr + 4) = make_float4(o[4], o[5], o[6], o[7]);
}

// ---- fused layer-2 tail for one batch b: LN1(row L-1) -> FFN1 -> FFN2+LN2+LNf+proj
__global__ __launch_bounds__(256) void tail_all(
    const float* __restrict__ x, const float* __restrict__ nx2,
    const float* __restrict__ l1g, const float* __restrict__ l1b,
    const float* __restrict__ c1W, const float* __restrict__ c1b,
    const float* __restrict__ c2W, const float* __restrict__ c2b,
    const float* __restrict__ ln2g, const float* __restrict__ ln2b,
    const float* __restrict__ nfg, const float* __restrict__ nfb,
    const float* __restrict__ projW, const float* __restrict__ projb,
    float* __restrict__ out)
{
    int b = blockIdx.x, d = threadIdx.x;
    __shared__ float t1s[DM];
    __shared__ float hs[DFF];
    __shared__ float sh[256];

    // LN1 of row L-1 plus attention residual
    float v = x[((size_t)(b * LQ + LQ - 1)) * DM + d] + nx2[b * DM + d];
    float mean = blockSum256(v, sh) * (1.0f / DM);
    float df = v - mean;
    float var = blockSum256(df * df, sh) * (1.0f / DM);
    float t1 = df * rsqrtf(var + 1e-5f) * l1g[d] + l1b[d];
    t1s[d] = t1;
    __syncthreads();

    // FFN1 + gelu
    for (int t = 0; t < DFF / 256; t++) {
        int j = t * 256 + d;
        float acc = c1b[j];
        #pragma unroll 4
        for (int k = 0; k < DM; k++) acc += t1s[k] * c1W[(size_t)k * DFF + j];
        hs[j] = gelu_exact(acc);
    }
    __syncthreads();

    // FFN2 + LN2 + final LN + proj
    float acc = c2b[d];
    #pragma unroll 4
    for (int j = 0; j < DFF; j++) acc += hs[j] * c2W[(size_t)j * DM + d];
    float val = t1 + acc;
    float mean2 = blockSum256(val, sh) * (1.0f / DM);
    float d2 = val - mean2;
    float var2 = blockSum256(d2 * d2, sh) * (1.0f / DM);
    float t2 = d2 * rsqrtf(var2 + 1e-5f) * ln2g[d] + ln2b[d];
    float mean3 = blockSum256(t2, sh) * (1.0f / DM);
    float d3 = t2 - mean3;
    float var3 = blockSum256(d3 * d3, sh) * (1.0f / DM);
    float t3 = d3 * rsqrtf(var3 + 1e-5f) * nfg[d] + nfb[d];
    float s = blockSum256(t3 * projW[d], sh);
    if (d == 0) out[b] = s + projb[0];
}

// ---------------- host ----------------------------------------------------------
extern "C" void kernel_launch(void* const* d_in, const int* in_sizes, int n_in,
                              void* d_out, int out_size)
{
    const float* x_enc  = (const float*)d_in[0];
    const int*   idxs   = (const int*)  d_in[1];
    const float* emb_W  = (const float*)d_in[2];
    const float* emb_b  = (const float*)d_in[3];
    const float* Wq     = (const float*)d_in[4];
    const float* bq     = (const float*)d_in[5];
    const float* Wk     = (const float*)d_in[6];
    const float* Wv     = (const float*)d_in[8];
    const float* bv     = (const float*)d_in[9];
    const float* Wo     = (const float*)d_in[10];
    const float* bo     = (const float*)d_in[11];
    const float* c1_W   = (const float*)d_in[12];
    const float* c1_b   = (const float*)d_in[13];
    const float* c2_W   = (const float*)d_in[14];
    const float* c2_b   = (const float*)d_in[15];
    const float* ln1_g  = (const float*)d_in[16];
    const float* ln1_b  = (const float*)d_in[17];
    const float* ln2_g  = (const float*)d_in[18];
    const float* ln2_b  = (const float*)d_in[19];
    const float* nf_g   = (const float*)d_in[20];
    const float* nf_b   = (const float*)d_in[21];
    const float* proj_W = (const float*)d_in[22];
    const float* proj_b = (const float*)d_in[23];
    float* out = (float*)d_out;

    float *px, *pz, *phid, *py, *pys, *pM, *pnx2;
    float *pA, *pw2, *pD, *ppm, *pps, *ppxb;
    int* ptop;
    cudaGetSymbolAddress((void**)&px,    g_x);
    cudaGetSymbolAddress((void**)&pz,    g_z);
    cudaGetSymbolAddress((void**)&phid,  g_hid);
    cudaGetSymbolAddress((void**)&py,    g_y);
    cudaGetSymbolAddress((void**)&pys,   g_ysplit);
    cudaGetSymbolAddress((void**)&pM,    g_M);
    cudaGetSymbolAddress((void**)&ptop,  g_top);
    cudaGetSymbolAddress((void**)&pnx2,  g_nx2);
    cudaGetSymbolAddress((void**)&pA,    g_A);
    cudaGetSymbolAddress((void**)&pw2,   g_w2);
    cudaGetSymbolAddress((void**)&pD,    g_D);
    cudaGetSymbolAddress((void**)&ppm,   g_pm);
    cudaGetSymbolAddress((void**)&pps,   g_ps);
    cudaGetSymbolAddress((void**)&ppxb,  g_pxb);

    cudaFuncSetAttribute(tgemm3<0,1,0>, cudaFuncAttributeMaxDynamicSharedMemorySize, TG_SMEM_BYTES);
    cudaFuncSetAttribute(tgemm3<1,1,0>, cudaFuncAttributeMaxDynamicSharedMemorySize, TG_SMEM_BYTES);
    cudaFuncSetAttribute(tgemm3<0,0,0>, cudaFuncAttributeMaxDynamicSharedMemorySize, TG_SMEM_BYTES);
    cudaFuncSetAttribute(tgemm3<0,0,1>, cudaFuncAttributeMaxDynamicSharedMemorySize, TG_SMEM_BYTES);

    // launch 1: embedding  [8192,32]@[32,256]+b
    tgemm3<0,1,0><<<dim3(DM / 128, ROWS / 128), 256, TG_SMEM_BYTES>>>(
        x_enc, emb_W, emb_b, px, ROWS, DM, 32);

    for (int l = 0; l < 2; l++) {
        const float* wq  = Wq + (size_t)l * DM * HD;
        const float* bql = bq + l * HD;
        const float* wk  = Wk + (size_t)l * DM * HD;
        const float* wv  = Wv + (size_t)l * DM * HD;
        const float* bvl = bv + l * HD;
        const float* wo  = Wo + (size_t)l * HD * DM;
        const float* bol = bo + l * DM;
        const float* c1w = c1_W + (size_t)l * DM * DFF;
        const float* c1b = c1_b + l * DFF;
        const float* c2w = c2_W + (size_t)l * DFF * DM;
        const float* c2b = c2_b + l * DM;
        const float* l1g = ln1_g + l * DM;
        const float* l1b = ln1_b + l * DM;
        const float* l2g = ln2_g + l * DM;
        const float* l2b = ln2_b + l * DM;
        float* pAl  = pA  + (size_t)l * DM * HD;
        float* pw2l = pw2 + (size_t)l * HH * DM;

        precomp_A<<<dim3(2, 2, 8), 256>>>(wq, wk, pAl);
        precomp_w2<<<256, 256>>>(wk, bql, pw2l);

        // launch 4 (l=0): dominant GEMM — keeps the ncu capture slot (control)
        tgemm3<0,0,0><<<dim3(HD / 128, ROWS / 128), 256, TG_SMEM_BYTES>>>(
            px, pAl, (const float*)nullptr, pz, ROWS, HD, DM);

        dvec_kernel<<<ROWS / 8, 256>>>(px, pw2l, pD);
        compute_M2<<<ROWS / 8, 256>>>(pz, px, idxs, pD, pM);
        // init scatter destination off the critical path
        if (l == 0) cudaMemsetAsync(py, 0, (size_t)ROWS * DM * sizeof(float));
        else        fill_bias_kernel<<<BQ * DM / 256, 256>>>(pnx2, bol, BQ);
        top5_kernel<<<BQ * HH, 256>>>(pM, ptop);
        ctxA<<<BQ * HH * NCH, 256>>>(pz, px, ptop, pD, ppm, pps, ppxb, l);
        ctxB2<<<BQ * HH, 256>>>(wv, bvl, ptop, ppm, pps, ppxb, wo,
                                (l == 0) ? py : pnx2, l);

        if (l == 0) {
            add_ln_kernel<<<ROWS / 8, 256>>>(px, py, bol, l1g, l1b, ROWS);
            tgemm3<1,1,0><<<dim3(DFF / 128, ROWS / 128), 256, TG_SMEM_BYTES>>>(
                px, c1w, c1b, phid, ROWS, DFF, DM);
            tgemm3<0,0,1><<<dim3(DM / 128, ROWS / 128, 4), 256, TG_SMEM_BYTES>>>(
                phid, c2w, (const float*)nullptr, pys, ROWS, DM, DFF);
            add_ln4_kernel<<<ROWS / 8, 256>>>(px, pys, c2b, l2g, l2b, ROWS);
        } else {
            tail_all<<<BQ, 256>>>(px, pnx2, l1g, l1b, c1w, c1b, c2w, c2b,
                                  l2g, l2b, nf_g, nf_b, proj_W, proj_b, out);
        }
    }
    (void)in_sizes; (void)n_in; (void)out_size;
}

// round 16
// speedup vs baseline: 1.0956x; 1.0956x over previous
#include <cuda_runtime.h>
#include <math.h>
#include <stdint.h>

#define BQ   4
#define LQ   2048
#define DM   256
#define HH   8
#define HD   2048
#define DFF  1024
#define UK   40
#define NTOP 5
#define ROWS (BQ*LQ)
#define NCH  8
#define CHS  (LQ/NCH)

__device__ float g_x[ROWS*DM];
__device__ float g_z[ROWS*HD];
__device__ float g_hid[ROWS*DFF];
__device__ float g_y[ROWS*DM];
__device__ float g_M[BQ*HH*LQ];
__device__ int   g_top[BQ*HH*NTOP];
__device__ float g_ctx[BQ*HH*NTOP*DM];
__device__ float g_nx2[BQ*DM];
__device__ float g_A[2*DM*HD];
__device__ float g_w2[2*HH*DM];
__device__ float g_D[ROWS*HH];
__device__ float g_pm[BQ*HH*NCH*NTOP];
__device__ float g_ps[BQ*HH*NCH*NTOP];
__device__ float g_pxb[BQ*HH*NCH*NTOP*DM];

__device__ __forceinline__ float warpSum(float v) {
    #pragma unroll
    for (int o = 16; o > 0; o >>= 1) v += __shfl_xor_sync(0xffffffffu, v, o);
    return v;
}
__device__ __forceinline__ float warpMax(float v) {
    #pragma unroll
    for (int o = 16; o > 0; o >>= 1) v = fmaxf(v, __shfl_xor_sync(0xffffffffu, v, o));
    return v;
}
__device__ __forceinline__ float gelu_exact(float x) {
    return 0.5f * x * (1.0f + erff(x * 0.70710678118654752440f));
}
__device__ __forceinline__ float blockSum256(float v, float* sh) {
    int t = threadIdx.x;
    __syncthreads();
    sh[t] = v; __syncthreads();
    #pragma unroll
    for (int s = 128; s > 0; s >>= 1) {
        if (t < s) sh[t] += sh[t + s];
        __syncthreads();
    }
    return sh[0];
}
__device__ __forceinline__ void mma_tf32(float c[4], const uint32_t a[4],
                                         const uint32_t b[2]) {
    asm volatile(
        "mma.sync.aligned.m16n8k8.row.col.f32.tf32.tf32.f32 "
        "{%0,%1,%2,%3}, {%4,%5,%6,%7}, {%8,%9}, {%0,%1,%2,%3};\n"
        : "+f"(c[0]), "+f"(c[1]), "+f"(c[2]), "+f"(c[3])
        : "r"(a[0]), "r"(a[1]), "r"(a[2]), "r"(a[3]), "r"(b[0]), "r"(b[1]));
}
__device__ __forceinline__ float dot8(float4 a0, float4 a1, float4 b0, float4 b1) {
    return a0.x*b0.x + a0.y*b0.y + a0.z*b0.z + a0.w*b0.w
         + a1.x*b1.x + a1.y*b1.y + a1.z*b1.z + a1.w*b1.w;
}
__device__ __forceinline__ void split_tf32(float x, uint32_t& hi, uint32_t& lo) {
    hi = __float_as_uint(x) & 0xFFFFE000u;
    lo = __float_as_uint(x - __uint_as_float(hi));
}
__device__ __forceinline__ void cp_async16(void* smem_dst, const void* gsrc) {
    uint32_t s = (uint32_t)__cvta_generic_to_shared(smem_dst);
    asm volatile("cp.async.cg.shared.global [%0], [%1], 16;" :: "r"(s), "l"(gsrc));
}
#define CP_COMMIT() asm volatile("cp.async.commit_group;")
#define CP_WAIT1()  asm volatile("cp.async.wait_group 1;" ::: "memory")

// ------- 3xTF32 GEMM: fp32 smem, split at frag load, cp.async 3-stage ----------
#define TGK 16
#define ASTR 20
#define BSTR 136
#define A_FLOATS (128 * ASTR)
#define B_FLOATS (TGK * BSTR)
#define STG (A_FLOATS + B_FLOATS)
#define TG_SMEM_BYTES (3 * STG * 4)    // 56832

template<int ACT, int BIAS>
__global__ __launch_bounds__(256, 2) void tgemm3(
    const float* __restrict__ A, const float* __restrict__ B,
    const float* __restrict__ bias, float* __restrict__ C,
    int M, int N, int K)
{
    extern __shared__ float smem[];

    const int t = threadIdx.x;
    const int bm0 = blockIdx.y * 128;
    const int bn0 = blockIdx.x * 128;

    const int arow = t >> 2, acol = (t & 3) * 4;
    const int brow = t >> 5, bcol = (t & 31) * 4;
    const float* Ag = A + (size_t)(bm0 + arow) * K + acol;
    const float* Bg = B + (size_t)brow * N + bn0 + bcol;

    const int wid = t >> 5, lane = t & 31;
    const int wm = wid & 3, wn = wid >> 2;
    const int mrow = wm * 32, ncol = wn * 64;
    const int g = lane >> 2, kq = lane & 3;

    float acc[2][8][4];
    #pragma unroll
    for (int i = 0; i < 2; i++)
        #pragma unroll
        for (int j = 0; j < 8; j++)
            #pragma unroll
            for (int c = 0; c < 4; c++) acc[i][j][c] = 0.f;

    const int nIter = K / TGK;

    auto commit_stage = [&](int it) {
        if (it < nIter) {
            int st = it % 3;
            float* As = smem + st * STG;
            float* Bs = As + A_FLOATS;
            const float* Aq = Ag + it * TGK;
            const float* Bq = Bg + (size_t)(it * TGK) * N;
            cp_async16(&As[arow * ASTR + acol], Aq);
            cp_async16(&As[(arow + 64) * ASTR + acol], Aq + (size_t)64 * K);
            cp_async16(&Bs[brow * BSTR + bcol], Bq);
            cp_async16(&Bs[(brow + 8) * BSTR + bcol], Bq + (size_t)8 * N);
        }
        CP_COMMIT();
    };

    commit_stage(0);
    commit_stage(1);

    for (int it = 0; it < nIter; it++) {
        CP_WAIT1();
        __syncthreads();
        commit_stage(it + 2);

        const float* As = smem + (it % 3) * STG;
        const float* Bs = As + A_FLOATS;
        #pragma unroll
        for (int kk = 0; kk < TGK; kk += 8) {
            uint32_t ah[2][4], al[2][4];
            #pragma unroll
            for (int mt = 0; mt < 2; mt++) {
                int base = (mrow + mt * 16 + g) * ASTR + kk + kq;
                split_tf32(As[base],                ah[mt][0], al[mt][0]);
                split_tf32(As[base + 8 * ASTR],     ah[mt][1], al[mt][1]);
                split_tf32(As[base + 4],            ah[mt][2], al[mt][2]);
                split_tf32(As[base + 8 * ASTR + 4], ah[mt][3], al[mt][3]);
            }
            #pragma unroll
            for (int nt = 0; nt < 8; nt++) {
                int base = (kk + kq) * BSTR + ncol + nt * 8 + g;
                uint32_t bh[2], bl[2];
                split_tf32(Bs[base],            bh[0], bl[0]);
                split_tf32(Bs[base + 4 * BSTR], bh[1], bl[1]);
                #pragma unroll
                for (int mt = 0; mt < 2; mt++) {
                    mma_tf32(acc[mt][nt], ah[mt], bl);
                    mma_tf32(acc[mt][nt], al[mt], bh);
                    mma_tf32(acc[mt][nt], ah[mt], bh);
                }
            }
        }
    }

    #pragma unroll
    for (int mt = 0; mt < 2; mt++) {
        int row = bm0 + mrow + mt * 16 + g;
        #pragma unroll
        for (int nt = 0; nt < 8; nt++) {
            int col = bn0 + ncol + nt * 8 + 2 * kq;
            float b0 = 0.f, b1 = 0.f;
            if (BIAS) { b0 = bias[col]; b1 = bias[col + 1]; }
            float v0 = acc[mt][nt][0] + b0;
            float v1 = acc[mt][nt][1] + b1;
            float v2 = acc[mt][nt][2] + b0;
            float v3 = acc[mt][nt][3] + b1;
            if (ACT == 1) {
                v0 = gelu_exact(v0); v1 = gelu_exact(v1);
                v2 = gelu_exact(v2); v3 = gelu_exact(v3);
            }
            *(float2*)(C + (size_t)row * N + col)       = make_float2(v0, v1);
            *(float2*)(C + (size_t)(row + 8) * N + col) = make_float2(v2, v3);
        }
    }
}

// ---------------- A_h = Wq_h @ Wk_h^T  (fp32, exact)  grid (2,2,8) -------------
__global__ __launch_bounds__(256) void precomp_A(
    const float* __restrict__ Wq, const float* __restrict__ Wk,
    float* __restrict__ Aout)
{
    int h = blockIdx.z;
    int m0 = blockIdx.y * 128, n0 = blockIdx.x * 128;
    __shared__ float sa[8][128];
    __shared__ float sb[8][128];
    int t = threadIdx.x, tx = t & 15, ty = t >> 4;
    int lrow = t >> 1, lk = (t & 1) * 4;

    float acc[8][8];
    #pragma unroll
    for (int i = 0; i < 8; i++)
        #pragma unroll
        for (int j = 0; j < 8; j++) acc[i][j] = 0.f;

    for (int k0 = 0; k0 < DM; k0 += 8) {
        float4 a = *(const float4*)(Wq + (size_t)(m0 + lrow) * HD + h * DM + k0 + lk);
        float4 b = *(const float4*)(Wk + (size_t)(n0 + lrow) * HD + h * DM + k0 + lk);
        sa[lk + 0][lrow] = a.x; sa[lk + 1][lrow] = a.y;
        sa[lk + 2][lrow] = a.z; sa[lk + 3][lrow] = a.w;
        sb[lk + 0][lrow] = b.x; sb[lk + 1][lrow] = b.y;
        sb[lk + 2][lrow] = b.z; sb[lk + 3][lrow] = b.w;
        __syncthreads();
        #pragma unroll
        for (int kk = 0; kk < 8; kk++) {
            float ra[8], rb[8];
            #pragma unroll
            for (int i = 0; i < 8; i++) ra[i] = sa[kk][ty * 8 + i];
            #pragma unroll
            for (int j = 0; j < 8; j++) rb[j] = sb[kk][tx * 8 + j];
            #pragma unroll
            for (int i = 0; i < 8; i++)
                #pragma unroll
                for (int j = 0; j < 8; j++) acc[i][j] += ra[i] * rb[j];
        }
        __syncthreads();
    }
    #pragma unroll
    for (int i = 0; i < 8; i++)
        #pragma unroll
        for (int j = 0; j < 8; j++)
            Aout[(size_t)(m0 + ty * 8 + i) * HD + h * DM + n0 + tx * 8 + j] = acc[i][j];
}

__global__ void precomp_w2(const float* __restrict__ Wk,
                           const float* __restrict__ bq, float* __restrict__ w2)
{
    int gw = (blockIdx.x * 256 + threadIdx.x) >> 5;
    int lane = threadIdx.x & 31;
    int h = gw >> 8, m = gw & 255;
    const float* wr = Wk + (size_t)m * HD + h * DM + lane * 8;
    const float* br = bq + h * DM + lane * 8;
    float4 a0 = *(const float4*)wr, a1 = *(const float4*)(wr + 4);
    float4 b0 = *(const float4*)br, b1 = *(const float4*)(br + 4);
    float p = warpSum(dot8(a0, a1, b0, b1));
    if (lane == 0) w2[h * 256 + m] = p;
}

__global__ __launch_bounds__(256) void dvec_kernel(
    const float* __restrict__ x, const float* __restrict__ w2,
    float* __restrict__ D)
{
    __shared__ float ws[HH * DM];
    int t = threadIdx.x;
    for (int i = t; i < HH * DM; i += 256) ws[i] = w2[i];
    __syncthreads();
    int gw = (blockIdx.x * 256 + t) >> 5;
    int lane = t & 31;
    const float* xr = x + (size_t)gw * DM + lane * 8;
    float4 xa = *(const float4*)xr, xb = *(const float4*)(xr + 4);
    float out = 0.f;
    #pragma unroll
    for (int h = 0; h < 8; h++) {
        const float* wr = ws + h * DM + lane * 8;
        float4 w0 = *(const float4*)wr, w1 = *(const float4*)(wr + 4);
        float p = warpSum(dot8(xa, xb, w0, w1));
        if (lane == h) out = p;
    }
    if (lane < 8) D[(size_t)gw * HH + lane] = out;
}

__global__ __launch_bounds__(256) void compute_M2(
    const float* __restrict__ Z, const float* __restrict__ x,
    const int* __restrict__ idx, const float* __restrict__ D,
    float* __restrict__ Mout)
{
    int t = threadIdx.x, lane = t & 31;
    int gw = (blockIdx.x * 256 + t) >> 5;
    int l = gw & (LQ - 1), b = gw >> 11;

    float4 z0[8], z1[8];
    const float* zr = Z + (size_t)gw * HD;
    #pragma unroll
    for (int h = 0; h < 8; h++) {
        z0[h] = *(const float4*)(zr + h * DM + lane * 8);
        z1[h] = *(const float4*)(zr + h * DM + lane * 8 + 4);
    }
    float mx[8], sm[8];
    #pragma unroll
    for (int h = 0; h < 8; h++) { mx[h] = -3.4e38f; sm[h] = 0.f; }

    for (int u = 0; u < UK; u++) {
        int s = __ldg(&idx[l * UK + u]);
        const float* xr = x + ((size_t)(b * LQ + s)) * DM + lane * 8;
        float4 xa = *(const float4*)xr, xb = *(const float4*)(xr + 4);
        const float* dp = D + (size_t)(b * LQ + s) * HH;
        float p[8];
        #pragma unroll
        for (int h = 0; h < 8; h++) p[h] = dot8(z0[h], z1[h], xa, xb);
        #pragma unroll
        for (int h = 0; h < 8; h++) {
            p[h] = warpSum(p[h]) + __ldg(&dp[h]);
            mx[h] = fmaxf(mx[h], p[h]);
            sm[h] += p[h];
        }
    }
    float out = 0.f;
    #pragma unroll
    for (int h = 0; h < 8; h++)
        if (lane == h) out = mx[h] - sm[h] * (1.0f / LQ);
    if (lane < 8) Mout[((size_t)(b * 8 + lane)) * LQ + l] = out;
}

__global__ __launch_bounds__(256) void top5_kernel(
    const float* __restrict__ M, int* __restrict__ topi)
{
    int bh = blockIdx.x, tid = threadIdx.x;
    __shared__ float sM[LQ];
    __shared__ float sv[256];
    __shared__ int   si[256];
    for (int i = tid; i < LQ; i += 256) sM[i] = M[(size_t)bh * LQ + i];
    __syncthreads();
    for (int t = 0; t < NTOP; t++) {
        float best = -3.4e38f; int bi = LQ;
        for (int i = tid; i < LQ; i += 256) {
            float v = sM[i];
            if (v > best) { best = v; bi = i; }
        }
        sv[tid] = best; si[tid] = bi;
        __syncthreads();
        for (int s = 128; s > 0; s >>= 1) {
            if (tid < s) {
                if (sv[tid + s] > sv[tid] ||
                    (sv[tid + s] == sv[tid] && si[tid + s] < si[tid])) {
                    sv[tid] = sv[tid + s]; si[tid] = si[tid + s];
                }
            }
            __syncthreads();
        }
        if (tid == 0) { topi[bh * NTOP + t] = si[0]; sM[si[0]] = -3.4e38f; }
        __syncthreads();
    }
}

// ---- ctx phase A: one block per (b,h,chunk); partial softmax + partial xbar ---
__global__ __launch_bounds__(256) void ctxA(
    const float* __restrict__ Z, const float* __restrict__ x,
    const int* __restrict__ topi, const float* __restrict__ D,
    float* __restrict__ pm, float* __restrict__ ps, float* __restrict__ pxb,
    int only_last)
{
    int blk = blockIdx.x;
    int ch = blk & (NCH - 1), bh = blk >> 3;
    int h = bh & 7, b = bh >> 3;
    int tid = threadIdx.x, lane = tid & 31, w = tid >> 5;

    __shared__ float sc[NTOP][CHS];
    __shared__ float xbs[NTOP * DM];
    __shared__ float lmax[NTOP], lsum[NTOP];
    __shared__ int rtop[NTOP];
    if (tid < NTOP) rtop[tid] = topi[bh * NTOP + tid];
    __syncthreads();

    if (only_last) {
        bool has = false;
        #pragma unroll
        for (int i = 0; i < NTOP; i++) has |= (rtop[i] == LQ - 1);
        if (!has) return;
    }

    int s0 = ch * CHS;
    {
        float4 za[NTOP], zb[NTOP];
        #pragma unroll
        for (int i = 0; i < NTOP; i++) {
            int r = rtop[i];
            const float* zr = Z + ((size_t)(b * LQ + r)) * HD + h * DM + lane * 8;
            za[i] = *(const float4*)zr;
            zb[i] = *(const float4*)(zr + 4);
        }
        for (int sl = w; sl < CHS; sl += 8) {
            int s = s0 + sl;
            const float* xr = x + ((size_t)(b * LQ + s)) * DM + lane * 8;
            float4 xa = *(const float4*)xr, xb2 = *(const float4*)(xr + 4);
            float p[NTOP];
            #pragma unroll
            for (int i = 0; i < NTOP; i++) p[i] = dot8(za[i], zb[i], xa, xb2);
            #pragma unroll
            for (int i = 0; i < NTOP; i++) p[i] = warpSum(p[i]);
            if (lane == 0) {
                float dj = D[(size_t)(b * LQ + s) * HH + h];
                #pragma unroll
                for (int i = 0; i < NTOP; i++) sc[i][sl] = p[i] + dj;
            }
        }
    }
    __syncthreads();

    if (w < NTOP) {
        int i = w;
        float m = -3.4e38f;
        for (int sl = lane; sl < CHS; sl += 32) m = fmaxf(m, sc[i][sl]);
        m = warpMax(m);
        float ls = 0.f;
        for (int sl = lane; sl < CHS; sl += 32) {
            float e = expf(sc[i][sl] - m);
            sc[i][sl] = e;
            ls += e;
        }
        ls = warpSum(ls);
        if (lane == 0) { lmax[i] = m; lsum[i] = ls; }
    }
    for (int j = tid; j < NTOP * DM; j += 256) xbs[j] = 0.f;
    __syncthreads();

    {
        int sl0 = w * 32;
        float accv[NTOP][8];
        #pragma unroll
        for (int i = 0; i < NTOP; i++)
            #pragma unroll
            for (int j = 0; j < 8; j++) accv[i][j] = 0.f;
        for (int sl = sl0; sl < sl0 + 32; sl++) {
            const float* xr = x + ((size_t)(b * LQ + s0 + sl)) * DM + lane * 8;
            float4 xa = *(const float4*)xr, xb2 = *(const float4*)(xr + 4);
            float xv[8] = {xa.x, xa.y, xa.z, xa.w, xb2.x, xb2.y, xb2.z, xb2.w};
            #pragma unroll
            for (int i = 0; i < NTOP; i++) {
                float e = sc[i][sl];
                #pragma unroll
                for (int j = 0; j < 8; j++) accv[i][j] += e * xv[j];
            }
        }
        #pragma unroll
        for (int i = 0; i < NTOP; i++)
            #pragma unroll
            for (int j = 0; j < 8; j++)
                atomicAdd(&xbs[i * DM + lane * 8 + j], accv[i][j]);
    }
    __syncthreads();

    if (tid < NTOP) {
        pm[(size_t)(bh * NCH + ch) * NTOP + tid] = lmax[tid];
        ps[(size_t)(bh * NCH + ch) * NTOP + tid] = lsum[tid];
    }
    {
        int d = tid;
        #pragma unroll
        for (int i = 0; i < NTOP; i++)
            pxb[((size_t)(bh * NCH + ch) * NTOP + i) * DM + d] = xbs[i * DM + d];
    }
}

// ---- ctx phase B: combine chunk partials (flash rescale) + ctx matvec ---------
__global__ __launch_bounds__(256) void ctxB(
    const float* __restrict__ Wv, const float* __restrict__ bv,
    const int* __restrict__ topi,
    const float* __restrict__ pm, const float* __restrict__ ps,
    const float* __restrict__ pxb, float* __restrict__ ctx, int only_last)
{
    int bh = blockIdx.x;
    int h = bh & 7;
    int tid = threadIdx.x;

    __shared__ float xb[NTOP * DM];
    __shared__ float gmax[NTOP], ginv[NTOP];
    __shared__ float sscale[NTOP * NCH];
    __shared__ int rtop[NTOP];
    if (tid < NTOP) rtop[tid] = topi[bh * NTOP + tid];
    __syncthreads();

    if (only_last) {
        bool has = false;
        #pragma unroll
        for (int i = 0; i < NTOP; i++) has |= (rtop[i] == LQ - 1);
        if (!has) return;
    }

    if (tid < NTOP) {
        int i = tid;
        float gm = -3.4e38f;
        #pragma unroll
        for (int c = 0; c < NCH; c++)
            gm = fmaxf(gm, pm[(size_t)(bh * NCH + c) * NTOP + i]);
        gmax[i] = gm;
    }
    __syncthreads();
    if (tid < NTOP * NCH) {
        int i = tid / NCH, c = tid % NCH;
        sscale[i * NCH + c] =
            expf(pm[(size_t)(bh * NCH + c) * NTOP + i] - gmax[i]);
    }
    __syncthreads();
    if (tid < NTOP) {
        int i = tid;
        float tot = 0.f;
        #pragma unroll
        for (int c = 0; c < NCH; c++)
            tot += ps[(size_t)(bh * NCH + c) * NTOP + i] * sscale[i * NCH + c];
        ginv[i] = 1.0f / tot;
    }
    __syncthreads();

    {
        int d = tid;
        #pragma unroll
        for (int i = 0; i < NTOP; i++) {
            float acc = 0.f;
            #pragma unroll
            for (int c = 0; c < NCH; c++)
                acc += pxb[((size_t)(bh * NCH + c) * NTOP + i) * DM + d]
                     * sscale[i * NCH + c];
            xb[i * DM + d] = acc * ginv[i];
        }
    }
    __syncthreads();

    {
        int d = tid;
        float acc5[NTOP];
        float bvd = bv[h * DM + d];
        #pragma unroll
        for (int i = 0; i < NTOP; i++) acc5[i] = bvd;
        const float* wp = Wv + h * DM + d;
        #pragma unroll 4
        for (int c = 0; c < DM; c++) {
            float wv = wp[(size_t)c * HD];
            #pragma unroll
            for (int i = 0; i < NTOP; i++) acc5[i] += xb[i * DM + c] * wv;
        }
        #pragma unroll
        for (int i = 0; i < NTOP; i++)
            ctx[((size_t)bh * NTOP + i) * DM + d] = acc5[i];
    }
}

__global__ void fill_bias_kernel(float* __restrict__ out,
                                 const float* __restrict__ bias, int rows)
{
    int gid = blockIdx.x * blockDim.x + threadIdx.x;
    if (gid < rows * DM) out[gid] = bias[gid & (DM - 1)];
}

__global__ __launch_bounds__(256) void scatter_wo_kernel(
    const float* __restrict__ ctx, const int* __restrict__ topi,
    const float* __restrict__ Wo, float* __restrict__ newx)
{
    int blk = blockIdx.x;
    int i = blk % NTOP, bh = blk / NTOP;
    int h = bh & 7, b = bh >> 3;
    int d = threadIdx.x;
    __shared__ float cs[DM];
    cs[d] = ctx[(size_t)(bh * NTOP + i) * DM + d];
    __syncthreads();
    int r = topi[bh * NTOP + i];
    const float* w = Wo + (size_t)(h * DM) * DM + d;
    float acc = 0.f;
    #pragma unroll 4
    for (int c = 0; c < DM; c++) acc += cs[c] * w[(size_t)c * DM];
    atomicAdd(&newx[((size_t)b * LQ + r) * DM + d], acc);
}

__global__ __launch_bounds__(256) void scatter_wo_last_kernel(
    const float* __restrict__ ctx, const int* __restrict__ topi,
    const float* __restrict__ Wo, float* __restrict__ nx2)
{
    int blk = blockIdx.x;
    int i = blk % NTOP, bh = blk / NTOP;
    int h = bh & 7, b = bh >> 3;
    int r = topi[bh * NTOP + i];
    if (r != LQ - 1) return;
    int d = threadIdx.x;
    __shared__ float cs[DM];
    cs[d] = ctx[(size_t)(bh * NTOP + i) * DM + d];
    __syncthreads();
    const float* w = Wo + (size_t)(h * DM) * DM + d;
    float acc = 0.f;
    #pragma unroll 4
    for (int c = 0; c < DM; c++) acc += cs[c] * w[(size_t)c * DM];
    atomicAdd(&nx2[b * DM + d], acc);
}

// x = LN(x + y + bias?) ; bias may be null
__global__ __launch_bounds__(256) void add_ln_kernel(
    float* __restrict__ x, const float* __restrict__ y,
    const float* __restrict__ bias,
    const float* __restrict__ g, const float* __restrict__ bt, int rows)
{
    int gid = blockIdx.x * 256 + threadIdx.x;
    int warp = gid >> 5, lane = gid & 31;
    if (warp >= rows) return;
    float* xr = x + (size_t)warp * DM + lane * 8;
    const float* yr = y + (size_t)warp * DM + lane * 8;
    float4 x0 = *(float4*)xr, x1 = *(float4*)(xr + 4);
    float4 y0 = *(const float4*)yr, y1 = *(const float4*)(yr + 4);
    float v[8] = {x0.x+y0.x, x0.y+y0.y, x0.z+y0.z, x0.w+y0.w,
                  x1.x+y1.x, x1.y+y1.y, x1.z+y1.z, x1.w+y1.w};
    if (bias) {
        const float* br = bias + lane * 8;
        float4 b0 = *(const float4*)br, b1 = *(const float4*)(br + 4);
        float bb[8] = {b0.x,b0.y,b0.z,b0.w,b1.x,b1.y,b1.z,b1.w};
        #pragma unroll
        for (int t = 0; t < 8; t++) v[t] += bb[t];
    }
    float s = 0.f;
    #pragma unroll
    for (int t = 0; t < 8; t++) s += v[t];
    s = warpSum(s);
    float mean = s * (1.0f / DM);
    float vs = 0.f;
    #pragma unroll
    for (int t = 0; t < 8; t++) { float d = v[t] - mean; vs += d * d; }
    vs = warpSum(vs);
    float rstd = rsqrtf(vs * (1.0f / DM) + 1e-5f);
    float o[8];
    #pragma unroll
    for (int t = 0; t < 8; t++)
        o[t] = (v[t] - mean) * rstd * g[lane * 8 + t] + bt[lane * 8 + t];
    *(float4*)xr       = make_float4(o[0], o[1], o[2], o[3]);
    *(float4*)(xr + 4) = make_float4(o[4], o[5], o[6], o[7]);
}

// ---- fused layer-2 tail for one batch b: LN1(row L-1) -> FFN1 -> FFN2+LN2+LNf+proj
__global__ __launch_bounds__(256) void tail_all(
    const float* __restrict__ x, const float* __restrict__ nx2,
    const float* __restrict__ l1g, const float* __restrict__ l1b,
    const float* __restrict__ c1W, const float* __restrict__ c1b,
    const float* __restrict__ c2W, const float* __restrict__ c2b,
    const float* __restrict__ ln2g, const float* __restrict__ ln2b,
    const float* __restrict__ nfg, const float* __restrict__ nfb,
    const float* __restrict__ projW, const float* __restrict__ projb,
    float* __restrict__ out)
{
    int b = blockIdx.x, d = threadIdx.x;
    __shared__ float t1s[DM];
    __shared__ float hs[DFF];
    __shared__ float sh[256];

    float v = x[((size_t)(b * LQ + LQ - 1)) * DM + d] + nx2[b * DM + d];
    float mean = blockSum256(v, sh) * (1.0f / DM);
    float df = v - mean;
    float var = blockSum256(df * df, sh) * (1.0f / DM);
    float t1 = df * rsqrtf(var + 1e-5f) * l1g[d] + l1b[d];
    t1s[d] = t1;
    __syncthreads();

    for (int t = 0; t < DFF / 256; t++) {
        int j = t * 256 + d;
        float acc = c1b[j];
        #pragma unroll 4
        for (int k = 0; k < DM; k++) acc += t1s[k] * c1W[(size_t)k * DFF + j];
        hs[j] = gelu_exact(acc);
    }
    __syncthreads();

    float acc = c2b[d];
    #pragma unroll 4
    for (int j = 0; j < DFF; j++) acc += hs[j] * c2W[(size_t)j * DM + d];
    float val = t1 + acc;
    float mean2 = blockSum256(val, sh) * (1.0f / DM);
    float d2 = val - mean2;
    float var2 = blockSum256(d2 * d2, sh) * (1.0f / DM);
    float t2 = d2 * rsqrtf(var2 + 1e-5f) * ln2g[d] + ln2b[d];
    float mean3 = blockSum256(t2, sh) * (1.0f / DM);
    float d3 = t2 - mean3;
    float var3 = blockSum256(d3 * d3, sh) * (1.0f / DM);
    float t3 = d3 * rsqrtf(var3 + 1e-5f) * nfg[d] + nfb[d];
    float s = blockSum256(t3 * projW[d], sh);
    if (d == 0) out[b] = s + projb[0];
}

// ---------------- host ----------------------------------------------------------
extern "C" void kernel_launch(void* const* d_in, const int* in_sizes, int n_in,
                              void* d_out, int out_size)
{
    const float* x_enc  = (const float*)d_in[0];
    const int*   idxs   = (const int*)  d_in[1];
    const float* emb_W  = (const float*)d_in[2];
    const float* emb_b  = (const float*)d_in[3];
    const float* Wq     = (const float*)d_in[4];
    const float* bq     = (const float*)d_in[5];
    const float* Wk     = (const float*)d_in[6];
    const float* Wv     = (const float*)d_in[8];
    const float* bv     = (const float*)d_in[9];
    const float* Wo     = (const float*)d_in[10];
    const float* bo     = (const float*)d_in[11];
    const float* c1_W   = (const float*)d_in[12];
    const float* c1_b   = (const float*)d_in[13];
    const float* c2_W   = (const float*)d_in[14];
    const float* c2_b   = (const float*)d_in[15];
    const float* ln1_g  = (const float*)d_in[16];
    const float* ln1_b  = (const float*)d_in[17];
    const float* ln2_g  = (const float*)d_in[18];
    const float* ln2_b  = (const float*)d_in[19];
    const float* nf_g   = (const float*)d_in[20];
    const float* nf_b   = (const float*)d_in[21];
    const float* proj_W = (const float*)d_in[22];
    const float* proj_b = (const float*)d_in[23];
    float* out = (float*)d_out;

    float *px, *pz, *phid, *py, *pM, *pctx, *pnx2;
    float *pA, *pw2, *pD, *ppm, *pps, *ppxb;
    int* ptop;
    cudaGetSymbolAddress((void**)&px,    g_x);
    cudaGetSymbolAddress((void**)&pz,    g_z);
    cudaGetSymbolAddress((void**)&phid,  g_hid);
    cudaGetSymbolAddress((void**)&py,    g_y);
    cudaGetSymbolAddress((void**)&pM,    g_M);
    cudaGetSymbolAddress((void**)&ptop,  g_top);
    cudaGetSymbolAddress((void**)&pctx,  g_ctx);
    cudaGetSymbolAddress((void**)&pnx2,  g_nx2);
    cudaGetSymbolAddress((void**)&pA,    g_A);
    cudaGetSymbolAddress((void**)&pw2,   g_w2);
    cudaGetSymbolAddress((void**)&pD,    g_D);
    cudaGetSymbolAddress((void**)&ppm,   g_pm);
    cudaGetSymbolAddress((void**)&pps,   g_ps);
    cudaGetSymbolAddress((void**)&ppxb,  g_pxb);

    cudaFuncSetAttribute(tgemm3<0,1>, cudaFuncAttributeMaxDynamicSharedMemorySize, TG_SMEM_BYTES);
    cudaFuncSetAttribute(tgemm3<1,1>, cudaFuncAttributeMaxDynamicSharedMemorySize, TG_SMEM_BYTES);
    cudaFuncSetAttribute(tgemm3<0,0>, cudaFuncAttributeMaxDynamicSharedMemorySize, TG_SMEM_BYTES);

    // launch 1: embedding  [8192,32]@[32,256]+b
    tgemm3<0,1><<<dim3(DM / 128, ROWS / 128), 256, TG_SMEM_BYTES>>>(
        x_enc, emb_W, emb_b, px, ROWS, DM, 32);

    for (int l = 0; l < 2; l++) {
        const float* wq  = Wq + (size_t)l * DM * HD;
        const float* bql = bq + l * HD;
        const float* wk  = Wk + (size_t)l * DM * HD;
        const float* wv  = Wv + (size_t)l * DM * HD;
        const float* bvl = bv + l * HD;
        const float* wo  = Wo + (size_t)l * HD * DM;
        const float* bol = bo + l * DM;
        const float* c1w = c1_W + (size_t)l * DM * DFF;
        const float* c1b = c1_b + l * DFF;
        const float* c2w = c2_W + (size_t)l * DFF * DM;
        const float* c2b = c2_b + l * DM;
        const float* l1g = ln1_g + l * DM;
        const float* l1b = ln1_b + l * DM;
        const float* l2g = ln2_g + l * DM;
        const float* l2b = ln2_b + l * DM;
        float* pAl  = pA  + (size_t)l * DM * HD;
        float* pw2l = pw2 + (size_t)l * HH * DM;

        precomp_A<<<dim3(2, 2, 8), 256>>>(wq, wk, pAl);
        precomp_w2<<<256, 256>>>(wk, bql, pw2l);

        // launch 4 (l=0): dominant GEMM — keeps the ncu capture slot (control)
        tgemm3<0,0><<<dim3(HD / 128, ROWS / 128), 256, TG_SMEM_BYTES>>>(
            px, pAl, (const float*)nullptr, pz, ROWS, HD, DM);

        dvec_kernel<<<ROWS / 8, 256>>>(px, pw2l, pD);
        compute_M2<<<ROWS / 8, 256>>>(pz, px, idxs, pD, pM);
        // init scatter destination early (only gates scatter_wo)
        if (l == 0) cudaMemsetAsync(py, 0, (size_t)ROWS * DM * sizeof(float));
        else        fill_bias_kernel<<<BQ * DM / 256, 256>>>(pnx2, bol, BQ);
        top5_kernel<<<BQ * HH, 256>>>(pM, ptop);
        ctxA<<<BQ * HH * NCH, 256>>>(pz, px, ptop, pD, ppm, pps, ppxb, l);
        ctxB<<<BQ * HH, 256>>>(wv, bvl, ptop, ppm, pps, ppxb, pctx, l);

        if (l == 0) {
            scatter_wo_kernel<<<BQ * HH * NTOP, 256>>>(pctx, ptop, wo, py);
            add_ln_kernel<<<ROWS / 8, 256>>>(px, py, bol, l1g, l1b, ROWS);
            tgemm3<1,1><<<dim3(DFF / 128, ROWS / 128), 256, TG_SMEM_BYTES>>>(
                px, c1w, c1b, phid, ROWS, DFF, DM);
            tgemm3<0,1><<<dim3(DM / 128, ROWS / 128), 256, TG_SMEM_BYTES>>>(
                phid, c2w, c2b, py, ROWS, DM, DFF);
            add_ln_kernel<<<ROWS / 8, 256>>>(px, py, (const float*)nullptr,
                                             l2g, l2b, ROWS);
        } else {
            scatter_wo_last_kernel<<<BQ * HH * NTOP, 256>>>(pctx, ptop, wo, pnx2);
            tail_all<<<BQ, 256>>>(px, pnx2, l1g, l1b, c1w, c1b, c2w, c2b,
                                  l2g, l2b, nf_g, nf_b, proj_W, proj_b, out);
        }
    }
    (void)in_sizes; (void)n_in; (void)out_size;
}

// round 17
// speedup vs baseline: 1.1414x; 1.0418x over previous
#include <cuda_runtime.h>
#include <math.h>
#include <stdint.h>

#define BQ   4
#define LQ   2048
#define DM   256
#define HH   8
#define HD   2048
#define DFF  1024
#define UK   40
#define NTOP 5
#define ROWS (BQ*LQ)
#define NCH  8
#define CHS  (LQ/NCH)

__device__ float g_x[ROWS*DM];
__device__ float g_z[ROWS*HD];
__device__ float g_hid[ROWS*DFF];
__device__ float g_y[ROWS*DM];
__device__ float g_M[BQ*HH*LQ];
__device__ int   g_top[BQ*HH*NTOP];
__device__ float g_ctx[BQ*HH*NTOP*DM];
__device__ float g_nx2[BQ*DM];
__device__ float g_A[2*DM*HD];
__device__ float g_w2[2*HH*DM];
__device__ float g_D[ROWS*HH];
__device__ float g_pm[BQ*HH*NCH*NTOP];
__device__ float g_ps[BQ*HH*NCH*NTOP];
__device__ float g_pxb[BQ*HH*NCH*NTOP*DM];

__device__ __forceinline__ float warpSum(float v) {
    #pragma unroll
    for (int o = 16; o > 0; o >>= 1) v += __shfl_xor_sync(0xffffffffu, v, o);
    return v;
}
__device__ __forceinline__ float warpMax(float v) {
    #pragma unroll
    for (int o = 16; o > 0; o >>= 1) v = fmaxf(v, __shfl_xor_sync(0xffffffffu, v, o));
    return v;
}
__device__ __forceinline__ float gelu_exact(float x) {
    return 0.5f * x * (1.0f + erff(x * 0.70710678118654752440f));
}
__device__ __forceinline__ float blockSum256(float v, float* sh) {
    int t = threadIdx.x;
    __syncthreads();
    sh[t] = v; __syncthreads();
    #pragma unroll
    for (int s = 128; s > 0; s >>= 1) {
        if (t < s) sh[t] += sh[t + s];
        __syncthreads();
    }
    return sh[0];
}
__device__ __forceinline__ void mma_tf32(float c[4], const uint32_t a[4],
                                         const uint32_t b[2]) {
    asm volatile(
        "mma.sync.aligned.m16n8k8.row.col.f32.tf32.tf32.f32 "
        "{%0,%1,%2,%3}, {%4,%5,%6,%7}, {%8,%9}, {%0,%1,%2,%3};\n"
        : "+f"(c[0]), "+f"(c[1]), "+f"(c[2]), "+f"(c[3])
        : "r"(a[0]), "r"(a[1]), "r"(a[2]), "r"(a[3]), "r"(b[0]), "r"(b[1]));
}
__device__ __forceinline__ float dot8(float4 a0, float4 a1, float4 b0, float4 b1) {
    return a0.x*b0.x + a0.y*b0.y + a0.z*b0.z + a0.w*b0.w
         + a1.x*b1.x + a1.y*b1.y + a1.z*b1.z + a1.w*b1.w;
}
__device__ __forceinline__ void split_tf32(float x, uint32_t& hi, uint32_t& lo) {
    hi = __float_as_uint(x) & 0xFFFFE000u;
    lo = __float_as_uint(x - __uint_as_float(hi));
}
__device__ __forceinline__ void cp_async16(void* smem_dst, const void* gsrc) {
    uint32_t s = (uint32_t)__cvta_generic_to_shared(smem_dst);
    asm volatile("cp.async.cg.shared.global [%0], [%1], 16;" :: "r"(s), "l"(gsrc));
}
#define CP_COMMIT() asm volatile("cp.async.commit_group;")
#define CP_WAIT1()  asm volatile("cp.async.wait_group 1;" ::: "memory")

// ------- 3xTF32 GEMM: fp32 smem, split at frag load, cp.async 3-stage ----------
#define TGK 16
#define ASTR 20
#define BSTR 136
#define A_FLOATS (128 * ASTR)
#define B_FLOATS (TGK * BSTR)
#define STG (A_FLOATS + B_FLOATS)
#define TG_SMEM_BYTES (3 * STG * 4)    // 56832

template<int ACT, int BIAS>
__global__ __launch_bounds__(256, 2) void tgemm3(
    const float* __restrict__ A, const float* __restrict__ B,
    const float* __restrict__ bias, float* __restrict__ C,
    int M, int N, int K)
{
    extern __shared__ float smem[];

    const int t = threadIdx.x;
    const int bm0 = blockIdx.y * 128;
    const int bn0 = blockIdx.x * 128;

    const int arow = t >> 2, acol = (t & 3) * 4;
    const int brow = t >> 5, bcol = (t & 31) * 4;
    const float* Ag = A + (size_t)(bm0 + arow) * K + acol;
    const float* Bg = B + (size_t)brow * N + bn0 + bcol;

    const int wid = t >> 5, lane = t & 31;
    const int wm = wid & 3, wn = wid >> 2;
    const int mrow = wm * 32, ncol = wn * 64;
    const int g = lane >> 2, kq = lane & 3;

    float acc[2][8][4];
    #pragma unroll
    for (int i = 0; i < 2; i++)
        #pragma unroll
        for (int j = 0; j < 8; j++)
            #pragma unroll
            for (int c = 0; c < 4; c++) acc[i][j][c] = 0.f;

    const int nIter = K / TGK;

    auto commit_stage = [&](int it) {
        if (it < nIter) {
            int st = it % 3;
            float* As = smem + st * STG;
            float* Bs = As + A_FLOATS;
            const float* Aq = Ag + it * TGK;
            const float* Bq = Bg + (size_t)(it * TGK) * N;
            cp_async16(&As[arow * ASTR + acol], Aq);
            cp_async16(&As[(arow + 64) * ASTR + acol], Aq + (size_t)64 * K);
            cp_async16(&Bs[brow * BSTR + bcol], Bq);
            cp_async16(&Bs[(brow + 8) * BSTR + bcol], Bq + (size_t)8 * N);
        }
        CP_COMMIT();
    };

    commit_stage(0);
    commit_stage(1);

    for (int it = 0; it < nIter; it++) {
        CP_WAIT1();
        __syncthreads();
        commit_stage(it + 2);

        const float* As = smem + (it % 3) * STG;
        const float* Bs = As + A_FLOATS;
        #pragma unroll
        for (int kk = 0; kk < TGK; kk += 8) {
            uint32_t ah[2][4], al[2][4];
            #pragma unroll
            for (int mt = 0; mt < 2; mt++) {
                int base = (mrow + mt * 16 + g) * ASTR + kk + kq;
                split_tf32(As[base],                ah[mt][0], al[mt][0]);
                split_tf32(As[base + 8 * ASTR],     ah[mt][1], al[mt][1]);
                split_tf32(As[base + 4],            ah[mt][2], al[mt][2]);
                split_tf32(As[base + 8 * ASTR + 4], ah[mt][3], al[mt][3]);
            }
            #pragma unroll
            for (int nt = 0; nt < 8; nt++) {
                int base = (kk + kq) * BSTR + ncol + nt * 8 + g;
                uint32_t bh[2], bl[2];
                split_tf32(Bs[base],            bh[0], bl[0]);
                split_tf32(Bs[base + 4 * BSTR], bh[1], bl[1]);
                #pragma unroll
                for (int mt = 0; mt < 2; mt++) {
                    mma_tf32(acc[mt][nt], ah[mt], bl);
                    mma_tf32(acc[mt][nt], al[mt], bh);
                    mma_tf32(acc[mt][nt], ah[mt], bh);
                }
            }
        }
    }

    #pragma unroll
    for (int mt = 0; mt < 2; mt++) {
        int row = bm0 + mrow + mt * 16 + g;
        #pragma unroll
        for (int nt = 0; nt < 8; nt++) {
            int col = bn0 + ncol + nt * 8 + 2 * kq;
            float b0 = 0.f, b1 = 0.f;
            if (BIAS) { b0 = bias[col]; b1 = bias[col + 1]; }
            float v0 = acc[mt][nt][0] + b0;
            float v1 = acc[mt][nt][1] + b1;
            float v2 = acc[mt][nt][2] + b0;
            float v3 = acc[mt][nt][3] + b1;
            if (ACT == 1) {
                v0 = gelu_exact(v0); v1 = gelu_exact(v1);
                v2 = gelu_exact(v2); v3 = gelu_exact(v3);
            }
            *(float2*)(C + (size_t)row * N + col)       = make_float2(v0, v1);
            *(float2*)(C + (size_t)(row + 8) * N + col) = make_float2(v2, v3);
        }
    }
}

// ---- A_h = Wq_h @ Wk_h^T (fp32, exact): 64x64 tiles, 4x4/thread, grid (4,4,8) -
__global__ __launch_bounds__(256) void precomp_A(
    const float* __restrict__ Wq, const float* __restrict__ Wk,
    float* __restrict__ Aout)
{
    int h = blockIdx.z;
    int m0 = blockIdx.y * 64, n0 = blockIdx.x * 64;
    __shared__ float sa[8][64];
    __shared__ float sb[8][64];
    int t = threadIdx.x, tx = t & 15, ty = t >> 4;
    int lrow = t >> 2, lk = (t & 3) * 2;

    float acc[4][4];
    #pragma unroll
    for (int i = 0; i < 4; i++)
        #pragma unroll
        for (int j = 0; j < 4; j++) acc[i][j] = 0.f;

    for (int k0 = 0; k0 < DM; k0 += 8) {
        float2 a = *(const float2*)(Wq + (size_t)(m0 + lrow) * HD + h * DM + k0 + lk);
        float2 b = *(const float2*)(Wk + (size_t)(n0 + lrow) * HD + h * DM + k0 + lk);
        sa[lk + 0][lrow] = a.x; sa[lk + 1][lrow] = a.y;
        sb[lk + 0][lrow] = b.x; sb[lk + 1][lrow] = b.y;
        __syncthreads();
        #pragma unroll
        for (int kk = 0; kk < 8; kk++) {
            float ra[4], rb[4];
            #pragma unroll
            for (int i = 0; i < 4; i++) ra[i] = sa[kk][ty * 4 + i];
            #pragma unroll
            for (int j = 0; j < 4; j++) rb[j] = sb[kk][tx * 4 + j];
            #pragma unroll
            for (int i = 0; i < 4; i++)
                #pragma unroll
                for (int j = 0; j < 4; j++) acc[i][j] += ra[i] * rb[j];
        }
        __syncthreads();
    }
    #pragma unroll
    for (int i = 0; i < 4; i++)
        #pragma unroll
        for (int j = 0; j < 4; j++)
            Aout[(size_t)(m0 + ty * 4 + i) * HD + h * DM + n0 + tx * 4 + j] = acc[i][j];
}

__global__ void precomp_w2(const float* __restrict__ Wk,
                           const float* __restrict__ bq, float* __restrict__ w2)
{
    int gw = (blockIdx.x * 256 + threadIdx.x) >> 5;
    int lane = threadIdx.x & 31;
    int h = gw >> 8, m = gw & 255;
    const float* wr = Wk + (size_t)m * HD + h * DM + lane * 8;
    const float* br = bq + h * DM + lane * 8;
    float4 a0 = *(const float4*)wr, a1 = *(const float4*)(wr + 4);
    float4 b0 = *(const float4*)br, b1 = *(const float4*)(br + 4);
    float p = warpSum(dot8(a0, a1, b0, b1));
    if (lane == 0) w2[h * 256 + m] = p;
}

__global__ __launch_bounds__(256) void dvec_kernel(
    const float* __restrict__ x, const float* __restrict__ w2,
    float* __restrict__ D)
{
    __shared__ float ws[HH * DM];
    int t = threadIdx.x;
    for (int i = t; i < HH * DM; i += 256) ws[i] = w2[i];
    __syncthreads();
    int gw = (blockIdx.x * 256 + t) >> 5;
    int lane = t & 31;
    const float* xr = x + (size_t)gw * DM + lane * 8;
    float4 xa = *(const float4*)xr, xb = *(const float4*)(xr + 4);
    float out = 0.f;
    #pragma unroll
    for (int h = 0; h < 8; h++) {
        const float* wr = ws + h * DM + lane * 8;
        float4 w0 = *(const float4*)wr, w1 = *(const float4*)(wr + 4);
        float p = warpSum(dot8(xa, xb, w0, w1));
        if (lane == h) out = p;
    }
    if (lane < 8) D[(size_t)gw * HH + lane] = out;
}

__global__ __launch_bounds__(256) void compute_M2(
    const float* __restrict__ Z, const float* __restrict__ x,
    const int* __restrict__ idx, const float* __restrict__ D,
    float* __restrict__ Mout)
{
    int t = threadIdx.x, lane = t & 31;
    int gw = (blockIdx.x * 256 + t) >> 5;
    int l = gw & (LQ - 1), b = gw >> 11;

    float4 z0[8], z1[8];
    const float* zr = Z + (size_t)gw * HD;
    #pragma unroll
    for (int h = 0; h < 8; h++) {
        z0[h] = *(const float4*)(zr + h * DM + lane * 8);
        z1[h] = *(const float4*)(zr + h * DM + lane * 8 + 4);
    }
    float mx[8], sm[8];
    #pragma unroll
    for (int h = 0; h < 8; h++) { mx[h] = -3.4e38f; sm[h] = 0.f; }

    for (int u = 0; u < UK; u++) {
        int s = __ldg(&idx[l * UK + u]);
        const float* xr = x + ((size_t)(b * LQ + s)) * DM + lane * 8;
        float4 xa = *(const float4*)xr, xb = *(const float4*)(xr + 4);
        const float* dp = D + (size_t)(b * LQ + s) * HH;
        float p[8];
        #pragma unroll
        for (int h = 0; h < 8; h++) p[h] = dot8(z0[h], z1[h], xa, xb);
        #pragma unroll
        for (int h = 0; h < 8; h++) {
            p[h] = warpSum(p[h]) + __ldg(&dp[h]);
            mx[h] = fmaxf(mx[h], p[h]);
            sm[h] += p[h];
        }
    }
    float out = 0.f;
    #pragma unroll
    for (int h = 0; h < 8; h++)
        if (lane == h) out = mx[h] - sm[h] * (1.0f / LQ);
    if (lane < 8) Mout[((size_t)(b * 8 + lane)) * LQ + l] = out;
}

__global__ __launch_bounds__(256) void top5_kernel(
    const float* __restrict__ M, int* __restrict__ topi)
{
    int bh = blockIdx.x, tid = threadIdx.x;
    __shared__ float sM[LQ];
    __shared__ float sv[256];
    __shared__ int   si[256];
    for (int i = tid; i < LQ; i += 256) sM[i] = M[(size_t)bh * LQ + i];
    __syncthreads();
    for (int t = 0; t < NTOP; t++) {
        float best = -3.4e38f; int bi = LQ;
        for (int i = tid; i < LQ; i += 256) {
            float v = sM[i];
            if (v > best) { best = v; bi = i; }
        }
        sv[tid] = best; si[tid] = bi;
        __syncthreads();
        for (int s = 128; s > 0; s >>= 1) {
            if (tid < s) {
                if (sv[tid + s] > sv[tid] ||
                    (sv[tid + s] == sv[tid] && si[tid + s] < si[tid])) {
                    sv[tid] = sv[tid + s]; si[tid] = si[tid + s];
                }
            }
            __syncthreads();
        }
        if (tid == 0) { topi[bh * NTOP + t] = si[0]; sM[si[0]] = -3.4e38f; }
        __syncthreads();
    }
}

// ---- ctx phase A: one block per (b,h,chunk); partial softmax + partial xbar ---
__global__ __launch_bounds__(256) void ctxA(
    const float* __restrict__ Z, const float* __restrict__ x,
    const int* __restrict__ topi, const float* __restrict__ D,
    float* __restrict__ pm, float* __restrict__ ps, float* __restrict__ pxb,
    int only_last)
{
    int blk = blockIdx.x;
    int ch = blk & (NCH - 1), bh = blk >> 3;
    int h = bh & 7, b = bh >> 3;
    int tid = threadIdx.x, lane = tid & 31, w = tid >> 5;

    __shared__ float sc[NTOP][CHS];
    __shared__ float xbs[NTOP * DM];
    __shared__ float lmax[NTOP], lsum[NTOP];
    __shared__ int rtop[NTOP];
    if (tid < NTOP) rtop[tid] = topi[bh * NTOP + tid];
    __syncthreads();

    if (only_last) {
        bool has = false;
        #pragma unroll
        for (int i = 0; i < NTOP; i++) has |= (rtop[i] == LQ - 1);
        if (!has) return;
    }

    int s0 = ch * CHS;
    {
        float4 za[NTOP], zb[NTOP];
        #pragma unroll
        for (int i = 0; i < NTOP; i++) {
            int r = rtop[i];
            const float* zr = Z + ((size_t)(b * LQ + r)) * HD + h * DM + lane * 8;
            za[i] = *(const float4*)zr;
            zb[i] = *(const float4*)(zr + 4);
        }
        for (int sl = w; sl < CHS; sl += 8) {
            int s = s0 + sl;
            const float* xr = x + ((size_t)(b * LQ + s)) * DM + lane * 8;
            float4 xa = *(const float4*)xr, xb2 = *(const float4*)(xr + 4);
            float p[NTOP];
            #pragma unroll
            for (int i = 0; i < NTOP; i++) p[i] = dot8(za[i], zb[i], xa, xb2);
            #pragma unroll
            for (int i = 0; i < NTOP; i++) p[i] = warpSum(p[i]);
            if (lane == 0) {
                float dj = D[(size_t)(b * LQ + s) * HH + h];
                #pragma unroll
                for (int i = 0; i < NTOP; i++) sc[i][sl] = p[i] + dj;
            }
        }
    }
    __syncthreads();

    if (w < NTOP) {
        int i = w;
        float m = -3.4e38f;
        for (int sl = lane; sl < CHS; sl += 32) m = fmaxf(m, sc[i][sl]);
        m = warpMax(m);
        float ls = 0.f;
        for (int sl = lane; sl < CHS; sl += 32) {
            float e = expf(sc[i][sl] - m);
            sc[i][sl] = e;
            ls += e;
        }
        ls = warpSum(ls);
        if (lane == 0) { lmax[i] = m; lsum[i] = ls; }
    }
    for (int j = tid; j < NTOP * DM; j += 256) xbs[j] = 0.f;
    __syncthreads();

    {
        int sl0 = w * 32;
        float accv[NTOP][8];
        #pragma unroll
        for (int i = 0; i < NTOP; i++)
            #pragma unroll
            for (int j = 0; j < 8; j++) accv[i][j] = 0.f;
        for (int sl = sl0; sl < sl0 + 32; sl++) {
            const float* xr = x + ((size_t)(b * LQ + s0 + sl)) * DM + lane * 8;
            float4 xa = *(const float4*)xr, xb2 = *(const float4*)(xr + 4);
            float xv[8] = {xa.x, xa.y, xa.z, xa.w, xb2.x, xb2.y, xb2.z, xb2.w};
            #pragma unroll
            for (int i = 0; i < NTOP; i++) {
                float e = sc[i][sl];
                #pragma unroll
                for (int j = 0; j < 8; j++) accv[i][j] += e * xv[j];
            }
        }
        #pragma unroll
        for (int i = 0; i < NTOP; i++)
            #pragma unroll
            for (int j = 0; j < 8; j++)
                atomicAdd(&xbs[i * DM + lane * 8 + j], accv[i][j]);
    }
    __syncthreads();

    if (tid < NTOP) {
        pm[(size_t)(bh * NCH + ch) * NTOP + tid] = lmax[tid];
        ps[(size_t)(bh * NCH + ch) * NTOP + tid] = lsum[tid];
    }
    {
        int d = tid;
        #pragma unroll
        for (int i = 0; i < NTOP; i++)
            pxb[((size_t)(bh * NCH + ch) * NTOP + i) * DM + d] = xbs[i * DM + d];
    }
}

// ---- ctx phase B: combine chunk partials (flash rescale) + ctx matvec ---------
__global__ __launch_bounds__(256) void ctxB(
    const float* __restrict__ Wv, const float* __restrict__ bv,
    const int* __restrict__ topi,
    const float* __restrict__ pm, const float* __restrict__ ps,
    const float* __restrict__ pxb, float* __restrict__ ctx, int only_last)
{
    int bh = blockIdx.x;
    int h = bh & 7;
    int tid = threadIdx.x;

    __shared__ float xb[NTOP * DM];
    __shared__ float gmax[NTOP], ginv[NTOP];
    __shared__ float sscale[NTOP * NCH];
    __shared__ int rtop[NTOP];
    if (tid < NTOP) rtop[tid] = topi[bh * NTOP + tid];
    __syncthreads();

    if (only_last) {
        bool has = false;
        #pragma unroll
        for (int i = 0; i < NTOP; i++) has |= (rtop[i] == LQ - 1);
        if (!has) return;
    }

    if (tid < NTOP) {
        int i = tid;
        float gm = -3.4e38f;
        #pragma unroll
        for (int c = 0; c < NCH; c++)
            gm = fmaxf(gm, pm[(size_t)(bh * NCH + c) * NTOP + i]);
        gmax[i] = gm;
    }
    __syncthreads();
    if (tid < NTOP * NCH) {
        int i = tid / NCH, c = tid % NCH;
        sscale[i * NCH + c] =
            expf(pm[(size_t)(bh * NCH + c) * NTOP + i] - gmax[i]);
    }
    __syncthreads();
    if (tid < NTOP) {
        int i = tid;
        float tot = 0.f;
        #pragma unroll
        for (int c = 0; c < NCH; c++)
            tot += ps[(size_t)(bh * NCH + c) * NTOP + i] * sscale[i * NCH + c];
        ginv[i] = 1.0f / tot;
    }
    __syncthreads();

    {
        int d = tid;
        #pragma unroll
        for (int i = 0; i < NTOP; i++) {
            float acc = 0.f;
            #pragma unroll
            for (int c = 0; c < NCH; c++)
                acc += pxb[((size_t)(bh * NCH + c) * NTOP + i) * DM + d]
                     * sscale[i * NCH + c];
            xb[i * DM + d] = acc * ginv[i];
        }
    }
    __syncthreads();

    {
        int d = tid;
        float acc5[NTOP];
        float bvd = bv[h * DM + d];
        #pragma unroll
        for (int i = 0; i < NTOP; i++) acc5[i] = bvd;
        const float* wp = Wv + h * DM + d;
        #pragma unroll 4
        for (int c = 0; c < DM; c++) {
            float wv = wp[(size_t)c * HD];
            #pragma unroll
            for (int i = 0; i < NTOP; i++) acc5[i] += xb[i * DM + c] * wv;
        }
        #pragma unroll
        for (int i = 0; i < NTOP; i++)
            ctx[((size_t)bh * NTOP + i) * DM + d] = acc5[i];
    }
}

__global__ void fill_bias_kernel(float* __restrict__ out,
                                 const float* __restrict__ bias, int rows)
{
    int gid = blockIdx.x * blockDim.x + threadIdx.x;
    if (gid < rows * DM) out[gid] = bias[gid & (DM - 1)];
}

__global__ __launch_bounds__(256) void scatter_wo_kernel(
    const float* __restrict__ ctx, const int* __restrict__ topi,
    const float* __restrict__ Wo, float* __restrict__ newx)
{
    int blk = blockIdx.x;
    int i = blk % NTOP, bh = blk / NTOP;
    int h = bh & 7, b = bh >> 3;
    int d = threadIdx.x;
    __shared__ float cs[DM];
    cs[d] = ctx[(size_t)(bh * NTOP + i) * DM + d];
    __syncthreads();
    int r = topi[bh * NTOP + i];
    const float* w = Wo + (size_t)(h * DM) * DM + d;
    float acc = 0.f;
    #pragma unroll 4
    for (int c = 0; c < DM; c++) acc += cs[c] * w[(size_t)c * DM];
    atomicAdd(&newx[((size_t)b * LQ + r) * DM + d], acc);
}

__global__ __launch_bounds__(256) void scatter_wo_last_kernel(
    const float* __restrict__ ctx, const int* __restrict__ topi,
    const float* __restrict__ Wo, float* __restrict__ nx2)
{
    int blk = blockIdx.x;
    int i = blk % NTOP, bh = blk / NTOP;
    int h = bh & 7, b = bh >> 3;
    int r = topi[bh * NTOP + i];
    if (r != LQ - 1) return;
    int d = threadIdx.x;
    __shared__ float cs[DM];
    cs[d] = ctx[(size_t)(bh * NTOP + i) * DM + d];
    __syncthreads();
    const float* w = Wo + (size_t)(h * DM) * DM + d;
    float acc = 0.f;
    #pragma unroll 4
    for (int c = 0; c < DM; c++) acc += cs[c] * w[(size_t)c * DM];
    atomicAdd(&nx2[b * DM + d], acc);
}

// x = LN(x + y + bias?) ; bias may be null
__global__ __launch_bounds__(256) void add_ln_kernel(
    float* __restrict__ x, const float* __restrict__ y,
    const float* __restrict__ bias,
    const float* __restrict__ g, const float* __restrict__ bt, int rows)
{
    int gid = blockIdx.x * 256 + threadIdx.x;
    int warp = gid >> 5, lane = gid & 31;
    if (warp >= rows) return;
    float* xr = x + (size_t)warp * DM + lane * 8;
    const float* yr = y + (size_t)warp * DM + lane * 8;
    float4 x0 = *(float4*)xr, x1 = *(float4*)(xr + 4);
    float4 y0 = *(const float4*)yr, y1 = *(const float4*)(yr + 4);
    float v[8] = {x0.x+y0.x, x0.y+y0.y, x0.z+y0.z, x0.w+y0.w,
                  x1.x+y1.x, x1.y+y1.y, x1.z+y1.z, x1.w+y1.w};
    if (bias) {
        const float* br = bias + lane * 8;
        float4 b0 = *(const float4*)br, b1 = *(const float4*)(br + 4);
        float bb[8] = {b0.x,b0.y,b0.z,b0.w,b1.x,b1.y,b1.z,b1.w};
        #pragma unroll
        for (int t = 0; t < 8; t++) v[t] += bb[t];
    }
    float s = 0.f;
    #pragma unroll
    for (int t = 0; t < 8; t++) s += v[t];
    s = warpSum(s);
    float mean = s * (1.0f / DM);
    float vs = 0.f;
    #pragma unroll
    for (int t = 0; t < 8; t++) { float d = v[t] - mean; vs += d * d; }
    vs = warpSum(vs);
    float rstd = rsqrtf(vs * (1.0f / DM) + 1e-5f);
    float o[8];
    #pragma unroll
    for (int t = 0; t < 8; t++)
        o[t] = (v[t] - mean) * rstd * g[lane * 8 + t] + bt[lane * 8 + t];
    *(float4*)xr       = make_float4(o[0], o[1], o[2], o[3]);
    *(float4*)(xr + 4) = make_float4(o[4], o[5], o[6], o[7]);
}

// ---- fused layer-2 tail for one batch b ---------------------------------------
__global__ __launch_bounds__(256) void tail_all(
    const float* __restrict__ x, const float* __restrict__ nx2,
    const float* __restrict__ l1g, const float* __restrict__ l1b,
    const float* __restrict__ c1W, const float* __restrict__ c1b,
    const float* __restrict__ c2W, const float* __restrict__ c2b,
    const float* __restrict__ ln2g, const float* __restrict__ ln2b,
    const float* __restrict__ nfg, const float* __restrict__ nfb,
    const float* __restrict__ projW, const float* __restrict__ projb,
    float* __restrict__ out)
{
    int b = blockIdx.x, d = threadIdx.x;
    __shared__ float t1s[DM];
    __shared__ float hs[DFF];
    __shared__ float sh[256];

    float v = x[((size_t)(b * LQ + LQ - 1)) * DM + d] + nx2[b * DM + d];
    float mean = blockSum256(v, sh) * (1.0f / DM);
    float df = v - mean;
    float var = blockSum256(df * df, sh) * (1.0f / DM);
    float t1 = df * rsqrtf(var + 1e-5f) * l1g[d] + l1b[d];
    t1s[d] = t1;
    __syncthreads();

    for (int t = 0; t < DFF / 256; t++) {
        int j = t * 256 + d;
        float acc = c1b[j];
        #pragma unroll 4
        for (int k = 0; k < DM; k++) acc += t1s[k] * c1W[(size_t)k * DFF + j];
        hs[j] = gelu_exact(acc);
    }
    __syncthreads();

    float acc = c2b[d];
    #pragma unroll 4
    for (int j = 0; j < DFF; j++) acc += hs[j] * c2W[(size_t)j * DM + d];
    float val = t1 + acc;
    float mean2 = blockSum256(val, sh) * (1.0f / DM);
    float d2 = val - mean2;
    float var2 = blockSum256(d2 * d2, sh) * (1.0f / DM);
    float t2 = d2 * rsqrtf(var2 + 1e-5f) * ln2g[d] + ln2b[d];
    float mean3 = blockSum256(t2, sh) * (1.0f / DM);
    float d3 = t2 - mean3;
    float var3 = blockSum256(d3 * d3, sh) * (1.0f / DM);
    float t3 = d3 * rsqrtf(var3 + 1e-5f) * nfg[d] + nfb[d];
    float s = blockSum256(t3 * projW[d], sh);
    if (d == 0) out[b] = s + projb[0];
}

// ---------------- host ----------------------------------------------------------
extern "C" void kernel_launch(void* const* d_in, const int* in_sizes, int n_in,
                              void* d_out, int out_size)
{
    const float* x_enc  = (const float*)d_in[0];
    const int*   idxs   = (const int*)  d_in[1];
    const float* emb_W  = (const float*)d_in[2];
    const float* emb_b  = (const float*)d_in[3];
    const float* Wq     = (const float*)d_in[4];
    const float* bq     = (const float*)d_in[5];
    const float* Wk     = (const float*)d_in[6];
    const float* Wv     = (const float*)d_in[8];
    const float* bv     = (const float*)d_in[9];
    const float* Wo     = (const float*)d_in[10];
    const float* bo     = (const float*)d_in[11];
    const float* c1_W   = (const float*)d_in[12];
    const float* c1_b   = (const float*)d_in[13];
    const float* c2_W   = (const float*)d_in[14];
    const float* c2_b   = (const float*)d_in[15];
    const float* ln1_g  = (const float*)d_in[16];
    const float* ln1_b  = (const float*)d_in[17];
    const float* ln2_g  = (const float*)d_in[18];
    const float* ln2_b  = (const float*)d_in[19];
    const float* nf_g   = (const float*)d_in[20];
    const float* nf_b   = (const float*)d_in[21];
    const float* proj_W = (const float*)d_in[22];
    const float* proj_b = (const float*)d_in[23];
    float* out = (float*)d_out;

    float *px, *pz, *phid, *py, *pM, *pctx, *pnx2;
    float *pA, *pw2, *pD, *ppm, *pps, *ppxb;
    int* ptop;
    cudaGetSymbolAddress((void**)&px,    g_x);
    cudaGetSymbolAddress((void**)&pz,    g_z);
    cudaGetSymbolAddress((void**)&phid,  g_hid);
    cudaGetSymbolAddress((void**)&py,    g_y);
    cudaGetSymbolAddress((void**)&pM,    g_M);
    cudaGetSymbolAddress((void**)&ptop,  g_top);
    cudaGetSymbolAddress((void**)&pctx,  g_ctx);
    cudaGetSymbolAddress((void**)&pnx2,  g_nx2);
    cudaGetSymbolAddress((void**)&pA,    g_A);
    cudaGetSymbolAddress((void**)&pw2,   g_w2);
    cudaGetSymbolAddress((void**)&pD,    g_D);
    cudaGetSymbolAddress((void**)&ppm,   g_pm);
    cudaGetSymbolAddress((void**)&pps,   g_ps);
    cudaGetSymbolAddress((void**)&ppxb,  g_pxb);

    cudaFuncSetAttribute(tgemm3<0,1>, cudaFuncAttributeMaxDynamicSharedMemorySize, TG_SMEM_BYTES);
    cudaFuncSetAttribute(tgemm3<1,1>, cudaFuncAttributeMaxDynamicSharedMemorySize, TG_SMEM_BYTES);
    cudaFuncSetAttribute(tgemm3<0,0>, cudaFuncAttributeMaxDynamicSharedMemorySize, TG_SMEM_BYTES);

    // launch 1: embedding  [8192,32]@[32,256]+b
    tgemm3<0,1><<<dim3(DM / 128, ROWS / 128), 256, TG_SMEM_BYTES>>>(
        x_enc, emb_W, emb_b, px, ROWS, DM, 32);

    for (int l = 0; l < 2; l++) {
        const float* wq  = Wq + (size_t)l * DM * HD;
        const float* bql = bq + l * HD;
        const float* wk  = Wk + (size_t)l * DM * HD;
        const float* wv  = Wv + (size_t)l * DM * HD;
        const float* bvl = bv + l * HD;
        const float* wo  = Wo + (size_t)l * HD * DM;
        const float* bol = bo + l * DM;
        const float* c1w = c1_W + (size_t)l * DM * DFF;
        const float* c1b = c1_b + l * DFF;
        const float* c2w = c2_W + (size_t)l * DFF * DM;
        const float* c2b = c2_b + l * DM;
        const float* l1g = ln1_g + l * DM;
        const float* l1b = ln1_b + l * DM;
        const float* l2g = ln2_g + l * DM;
        const float* l2b = ln2_b + l * DM;
        float* pAl  = pA  + (size_t)l * DM * HD;
        float* pw2l = pw2 + (size_t)l * HH * DM;

        precomp_A<<<dim3(4, 4, 8), 256>>>(wq, wk, pAl);
        precomp_w2<<<256, 256>>>(wk, bql, pw2l);

        // launch 4 (l=0): dominant GEMM — keeps the ncu capture slot (control)
        tgemm3<0,0><<<dim3(HD / 128, ROWS / 128), 256, TG_SMEM_BYTES>>>(
            px, pAl, (const float*)nullptr, pz, ROWS, HD, DM);

        dvec_kernel<<<ROWS / 8, 256>>>(px, pw2l, pD);
        compute_M2<<<ROWS / 8, 256>>>(pz, px, idxs, pD, pM);
        if (l == 0) cudaMemsetAsync(py, 0, (size_t)ROWS * DM * sizeof(float));
        else        fill_bias_kernel<<<BQ * DM / 256, 256>>>(pnx2, bol, BQ);
        top5_kernel<<<BQ * HH, 256>>>(pM, ptop);
        ctxA<<<BQ * HH * NCH, 256>>>(pz, px, ptop, pD, ppm, pps, ppxb, l);
        ctxB<<<BQ * HH, 256>>>(wv, bvl, ptop, ppm, pps, ppxb, pctx, l);

        if (l == 0) {
            scatter_wo_kernel<<<BQ * HH * NTOP, 256>>>(pctx, ptop, wo, py);
            add_ln_kernel<<<ROWS / 8, 256>>>(px, py, bol, l1g, l1b, ROWS);
            tgemm3<1,1><<<dim3(DFF / 128, ROWS / 128), 256, TG_SMEM_BYTES>>>(
                px, c1w, c1b, phid, ROWS, DFF, DM);
            tgemm3<0,1><<<dim3(DM / 128, ROWS / 128), 256, TG_SMEM_BYTES>>>(
                phid, c2w, c2b, py, ROWS, DM, DFF);
            add_ln_kernel<<<ROWS / 8, 256>>>(px, py, (const float*)nullptr,
                                             l2g, l2b, ROWS);
        } else {
            scatter_wo_last_kernel<<<BQ * HH * NTOP, 256>>>(pctx, ptop, wo, pnx2);
            tail_all<<<BQ, 256>>>(px, pnx2, l1g, l1b, c1w, c1b, c2w, c2b,
                                  l2g, l2b, nf_g, nf_b, proj_W, proj_b, out);
        }
    }
    (void)in_sizes; (void)n_in; (void)out_size;
}